// round 1
// baseline (speedup 1.0000x reference)
#include <cuda_runtime.h>
#include <math.h>

#define Bsz 256
#define Tsz 128
#define Fsz 128
#define Hsz 512
#define BT  (Bsz * Tsz)          // 32768
#define KC  768                  // c_c(128) + h(512) + m(128)
#define N4H 2048                 // 4*H, gate-interleaved

// ----- device scratch (allocation-free rule: __device__ globals) -----
__device__ float g_h[Bsz * Hsz];
__device__ float g_c[Bsz * Hsz];
__device__ float g_xvec[Bsz * KC];                 // per-step [c_c | h_dec | m]
__device__ float g_gamma_h[(size_t)BT * Hsz];      // 64 MB
__device__ float g_gamma_x[BT * Fsz];
__device__ float g_alpha[BT * Fsz];
__device__ float g_inv_denom[Tsz];
__device__ float g_losspart[Tsz * 32];
__device__ float g_tdhT[Fsz * Hsz];                // td_h_W transposed [k][n]
__device__ float g_histT[Hsz * Fsz];               // hist_W transposed [k][f]
__device__ float g_featMT[Fsz * Fsz];              // masked feat, [j][f]
__device__ float g_wcT[2 * Fsz * Fsz];             // wc_W transposed [k][n]
__device__ float g_WcombT[KC * N4H];               // combined gate weights [k][n], gate-interleaved
__device__ float g_bcomb[N4H];

// ----------------------------------------------------------------------
// P0: weight transforms (one-time per launch; cheap)
// ----------------------------------------------------------------------
__global__ void prep_weights(const float* __restrict__ td_h_W,
                             const float* __restrict__ hist_W,
                             const float* __restrict__ feat_W,
                             const float* __restrict__ wc_W,
                             const float* __restrict__ W_ih,
                             const float* __restrict__ W_hh,
                             const float* __restrict__ b_ih,
                             const float* __restrict__ b_hh) {
    int stride = gridDim.x * blockDim.x;
    int tid = blockIdx.x * blockDim.x + threadIdx.x;
    for (int i = tid; i < Fsz * Hsz; i += stride) {          // tdhT[k*H+n] = td_h_W[n*F+k]
        int k = i / Hsz, n = i % Hsz;
        g_tdhT[i] = td_h_W[n * Fsz + k];
    }
    for (int i = tid; i < Hsz * Fsz; i += stride) {          // histT[k*F+f] = hist_W[f*H+k]
        int k = i / Fsz, f = i % Fsz;
        g_histT[i] = hist_W[f * Hsz + k];
    }
    for (int i = tid; i < Fsz * Fsz; i += stride) {          // featMT[j*F+f] = feat_W[f,j]*(j!=f)
        int j = i / Fsz, f = i % Fsz;
        g_featMT[i] = (j == f) ? 0.f : feat_W[f * Fsz + j];
    }
    for (int i = tid; i < 2 * Fsz * Fsz; i += stride) {      // wcT[k*F+n] = wc_W[n*2F+k]
        int k = i / Fsz, n = i % Fsz;
        g_wcT[i] = wc_W[n * 2 * Fsz + k];
    }
    for (int i = tid; i < KC * N4H; i += stride) {           // WcombT[k*2048+n]
        int k = i / N4H, n = i % N4H;
        int j = n >> 2, g = n & 3;
        int row = g * Hsz + j;                               // original row in W_ih/W_hh
        float v;
        if (k < Fsz)            v = W_ih[row * (2 * Fsz) + k];               // c_c part
        else if (k < Fsz + Hsz) v = W_hh[row * Hsz + (k - Fsz)];             // h part
        else                    v = W_ih[row * (2 * Fsz) + Fsz + (k - Fsz - Hsz)]; // m part
        g_WcombT[i] = v;
    }
    for (int i = tid; i < N4H; i += stride) {
        int j = i >> 2, g = i & 3;
        g_bcomb[i] = b_ih[g * Hsz + j] + b_hh[g * Hsz + j];
    }
}

// ----------------------------------------------------------------------
// gamma_x = exp(-relu(d * diag(td_x_W) + td_x_b))   (elementwise)
// ----------------------------------------------------------------------
__global__ void gammax_kernel(const float* __restrict__ d,
                              const float* __restrict__ td_x_W,
                              const float* __restrict__ td_x_b) {
    int i = blockIdx.x * blockDim.x + threadIdx.x;
    if (i < BT * Fsz) {
        int f = i & (Fsz - 1);
        float v = d[i] * td_x_W[f * Fsz + f] + td_x_b[f];
        g_gamma_x[i] = expf(-fmaxf(v, 0.f));
    }
}

// ----------------------------------------------------------------------
// gamma_h = exp(-relu(d @ td_h_W.T + b))  GEMM  M=BT, N=512, K=128
// tile 64x64, 256 threads, 4x4 micro
// ----------------------------------------------------------------------
__global__ void gammah_gemm(const float* __restrict__ d,
                            const float* __restrict__ td_h_b) {
    __shared__ float sA[64][33];
    __shared__ float sB[32][64];
    int m0 = blockIdx.x * 64;
    int n0 = blockIdx.y * 64;
    int tid = threadIdx.x;
    int tx = tid & 15, ty = tid >> 4;
    float acc[4][4] = {};
    for (int kk = 0; kk < Fsz; kk += 32) {
        for (int i = tid; i < 64 * 32; i += 256) {
            int r = i >> 5, k = i & 31;
            sA[r][k] = d[(size_t)(m0 + r) * Fsz + kk + k];
        }
        for (int i = tid; i < 32 * 64; i += 256) {
            int k = i >> 6, n = i & 63;
            sB[k][n] = g_tdhT[(kk + k) * Hsz + n0 + n];
        }
        __syncthreads();
#pragma unroll
        for (int k = 0; k < 32; k++) {
            float a[4], b[4];
#pragma unroll
            for (int i = 0; i < 4; i++) a[i] = sA[ty + i * 16][k];
#pragma unroll
            for (int j = 0; j < 4; j++) b[j] = sB[k][tx + j * 16];
#pragma unroll
            for (int i = 0; i < 4; i++)
#pragma unroll
                for (int j = 0; j < 4; j++) acc[i][j] += a[i] * b[j];
        }
        __syncthreads();
    }
#pragma unroll
    for (int i = 0; i < 4; i++)
#pragma unroll
        for (int j = 0; j < 4; j++) {
            int n = n0 + tx + j * 16;
            int row = m0 + ty + i * 16;
            g_gamma_h[(size_t)row * Hsz + n] = expf(-fmaxf(acc[i][j] + td_h_b[n], 0.f));
        }
}

// ----------------------------------------------------------------------
// alpha = sigmoid([gamma_x | m] @ wc_W.T + wc_b)  GEMM M=BT, N=128, K=256
// ----------------------------------------------------------------------
__global__ void alpha_gemm(const float* __restrict__ m,
                           const float* __restrict__ wc_b) {
    __shared__ float sA[64][33];
    __shared__ float sB[32][64];
    int m0 = blockIdx.x * 64;
    int n0 = blockIdx.y * 64;
    int tid = threadIdx.x;
    int tx = tid & 15, ty = tid >> 4;
    float acc[4][4] = {};
    for (int kk = 0; kk < 2 * Fsz; kk += 32) {
        for (int i = tid; i < 64 * 32; i += 256) {
            int r = i >> 5, k = i & 31;
            int kg = kk + k;
            float v = (kg < Fsz) ? g_gamma_x[(m0 + r) * Fsz + kg]
                                 : m[(size_t)(m0 + r) * Fsz + (kg - Fsz)];
            sA[r][k] = v;
        }
        for (int i = tid; i < 32 * 64; i += 256) {
            int k = i >> 6, n = i & 63;
            sB[k][n] = g_wcT[(kk + k) * Fsz + n0 + n];
        }
        __syncthreads();
#pragma unroll
        for (int k = 0; k < 32; k++) {
            float a[4], b[4];
#pragma unroll
            for (int i = 0; i < 4; i++) a[i] = sA[ty + i * 16][k];
#pragma unroll
            for (int j = 0; j < 4; j++) b[j] = sB[k][tx + j * 16];
#pragma unroll
            for (int i = 0; i < 4; i++)
#pragma unroll
                for (int j = 0; j < 4; j++) acc[i][j] += a[i] * b[j];
        }
        __syncthreads();
    }
#pragma unroll
    for (int i = 0; i < 4; i++)
#pragma unroll
        for (int j = 0; j < 4; j++) {
            int n = n0 + tx + j * 16;
            int row = m0 + ty + i * 16;
            float v = acc[i][j] + wc_b[n];
            g_alpha[row * Fsz + n] = 1.f / (1.f + expf(-v));
        }
}

// ----------------------------------------------------------------------
// per-time-step 1/denom
// ----------------------------------------------------------------------
__global__ void denom_kernel(const float* __restrict__ target_mask) {
    int t = blockIdx.x;
    float s = 0.f;
    for (int i = threadIdx.x; i < Bsz * Fsz; i += blockDim.x) {
        int b = i >> 7, f = i & 127;
        s += target_mask[((size_t)b * Tsz + t) * Fsz + f];
    }
    for (int o = 16; o; o >>= 1) s += __shfl_down_sync(0xffffffffu, s, o);
    __shared__ float red[8];
    if ((threadIdx.x & 31) == 0) red[threadIdx.x >> 5] = s;
    __syncthreads();
    if (threadIdx.x == 0) {
        float tot = 0.f;
        for (int i = 0; i < 8; i++) tot += red[i];
        g_inv_denom[t] = 1.f / (tot + 1e-8f);
    }
}

__global__ void init_state() {
    int i = blockIdx.x * blockDim.x + threadIdx.x;
    if (i < Bsz * Hsz) { g_h[i] = 0.f; g_c[i] = 0.f; }
}

// ----------------------------------------------------------------------
// K1 (per step): h_dec, x_hist GEMV-block, x_c, z_h, c_h, c_c, loss, imputation
// grid 32 blocks (8 batch rows each), 256 threads
// ----------------------------------------------------------------------
__global__ void step1_kernel(const float* __restrict__ x,
                             const float* __restrict__ m,
                             const float* __restrict__ target_x,
                             const float* __restrict__ target_mask,
                             const float* __restrict__ hist_b,
                             const float* __restrict__ feat_b,
                             float* __restrict__ out, int t) {
    __shared__ float sh[8][512];
    __shared__ float sxc[8][128];
    __shared__ float sred[8];
    int tid = threadIdx.x;
    int b0 = blockIdx.x * 8;

    // phase 1: h_dec = h * gamma_h ; stash to shared + xvec
    for (int i = tid; i < 8 * 512; i += 256) {
        int r = i >> 9, k = i & 511;
        int b = b0 + r;
        float hv = g_h[b * Hsz + k] * g_gamma_h[((size_t)b * Tsz + t) * Hsz + k];
        sh[r][k] = hv;
        g_xvec[b * KC + Fsz + k] = hv;
    }
    __syncthreads();

    int f = tid & 127;
    int r0 = tid >> 7;  // 0 or 1; thread handles rows r0, r0+2, r0+4, r0+6

    // phase 2: x_hist = h_dec @ hist_W.T + hist_b
    float acc[4] = {0.f, 0.f, 0.f, 0.f};
#pragma unroll 4
    for (int k = 0; k < 512; k++) {
        float w = g_histT[k * Fsz + f];
#pragma unroll
        for (int i = 0; i < 4; i++) acc[i] += sh[r0 + 2 * i][k] * w;
    }
    float xh[4], mv[4], xv[4];
    float hb = hist_b[f];
#pragma unroll
    for (int i = 0; i < 4; i++) {
        int r = r0 + 2 * i;
        int b = b0 + r;
        size_t base = ((size_t)b * Tsz + t) * Fsz + f;
        mv[i] = m[base];
        xv[i] = x[base];
        xh[i] = acc[i] + hb;
        float xc = mv[i] * xv[i] + (1.f - mv[i]) * xh[i];
        sxc[r][f] = xc;
        g_xvec[b * KC + (Fsz + Hsz) + f] = mv[i];  // m into xvec tail
    }
    __syncthreads();

    // phase 3: z_h = x_c @ featMT + feat_b ; combine ; loss
    float accz[4] = {0.f, 0.f, 0.f, 0.f};
#pragma unroll 4
    for (int j = 0; j < 128; j++) {
        float w = g_featMT[j * Fsz + f];
#pragma unroll
        for (int i = 0; i < 4; i++) accz[i] += sxc[r0 + 2 * i][j] * w;
    }
    float fb = feat_b[f];
    float lp = 0.f;
#pragma unroll
    for (int i = 0; i < 4; i++) {
        int r = r0 + 2 * i;
        int b = b0 + r;
        size_t base = ((size_t)b * Tsz + t) * Fsz + f;
        float z = accz[i] + fb;
        float a = g_alpha[base];
        float ch = a * z + (1.f - a) * xh[i];
        float cc = mv[i] * xv[i] + (1.f - mv[i]) * ch;
        g_xvec[b * KC + f] = cc;
        out[base] = cc;                       // imputation
        float ev = target_mask[base];
        float tg = target_x[base];
        float d1 = xh[i] - tg, d2 = z - tg, d3 = ch - tg;
        lp += ev * (d1 * d1 + d2 * d2 + d3 * d3);
    }
    // deterministic block reduce
    for (int o = 16; o; o >>= 1) lp += __shfl_down_sync(0xffffffffu, lp, o);
    if ((tid & 31) == 0) sred[tid >> 5] = lp;
    __syncthreads();
    if (tid == 0) {
        float tot = 0.f;
        for (int i = 0; i < 8; i++) tot += sred[i];
        g_losspart[t * 32 + blockIdx.x] = tot;
    }
}

// ----------------------------------------------------------------------
// K2 (per step): gates GEMM M=256, N=2048 (gate-interleaved), K=768 + LSTM epilogue
// grid (8, 32), 256 threads, tile 32x64, micro 2x4 (4 cols = the i,f,g,o quad)
// ----------------------------------------------------------------------
__global__ void step2_kernel() {
    __shared__ float sA[32][33];
    __shared__ float sB[32][64];
    int b0 = blockIdx.x * 32;
    int n0 = blockIdx.y * 64;
    int tid = threadIdx.x, tx = tid & 15, ty = tid >> 4;
    float acc[2][4] = {};
    for (int kk = 0; kk < KC; kk += 32) {
        for (int i = tid; i < 32 * 32; i += 256) {
            int r = i >> 5, k = i & 31;
            sA[r][k] = g_xvec[(b0 + r) * KC + kk + k];
        }
        for (int i = tid; i < 32 * 64; i += 256) {
            int k = i >> 6, n = i & 63;
            sB[k][n] = g_WcombT[(kk + k) * N4H + n0 + n];
        }
        __syncthreads();
#pragma unroll
        for (int k = 0; k < 32; k++) {
            float a0 = sA[ty][k];
            float a1 = sA[ty + 16][k];
            float4 bv = *reinterpret_cast<float4*>(&sB[k][tx * 4]);
            acc[0][0] += a0 * bv.x; acc[0][1] += a0 * bv.y;
            acc[0][2] += a0 * bv.z; acc[0][3] += a0 * bv.w;
            acc[1][0] += a1 * bv.x; acc[1][1] += a1 * bv.y;
            acc[1][2] += a1 * bv.z; acc[1][3] += a1 * bv.w;
        }
        __syncthreads();
    }
    int j = (n0 >> 2) + tx;      // hidden unit index
    float bi = g_bcomb[n0 + tx * 4 + 0];
    float bf = g_bcomb[n0 + tx * 4 + 1];
    float bg = g_bcomb[n0 + tx * 4 + 2];
    float bo = g_bcomb[n0 + tx * 4 + 3];
#pragma unroll
    for (int i = 0; i < 2; i++) {
        int b = b0 + ty + i * 16;
        float gi = acc[i][0] + bi;
        float gf = acc[i][1] + bf;
        float gg = acc[i][2] + bg;
        float go = acc[i][3] + bo;
        float si = 1.f / (1.f + expf(-gi));
        float sf = 1.f / (1.f + expf(-gf));
        float so = 1.f / (1.f + expf(-go));
        float tg = tanhf(gg);
        float cn = sf * g_c[b * Hsz + j] + si * tg;
        g_c[b * Hsz + j] = cn;
        g_h[b * Hsz + j] = so * tanhf(cn);
    }
}

// ----------------------------------------------------------------------
// final: loss = (sum_t inv_denom[t] * sum_blk part) / T   (deterministic order)
// ----------------------------------------------------------------------
__global__ void loss_final(float* __restrict__ out, int out_size) {
    __shared__ float s[128];
    int t = threadIdx.x;
    float v = 0.f;
    for (int b = 0; b < 32; b++) v += g_losspart[t * 32 + b];
    s[t] = v * g_inv_denom[t];
    __syncthreads();
    if (t == 0) {
        float tot = 0.f;
        for (int i = 0; i < 128; i++) tot += s[i];
        out[out_size - 1] = tot / (float)Tsz;
    }
}

// ----------------------------------------------------------------------
extern "C" void kernel_launch(void* const* d_in, const int* in_sizes, int n_in,
                              void* d_out, int out_size) {
    const float* x           = (const float*)d_in[0];
    const float* m           = (const float*)d_in[1];
    const float* d           = (const float*)d_in[2];
    const float* target_x    = (const float*)d_in[3];
    const float* target_mask = (const float*)d_in[4];
    const float* td_h_W      = (const float*)d_in[5];
    const float* td_h_b      = (const float*)d_in[6];
    const float* td_x_W      = (const float*)d_in[7];
    const float* td_x_b      = (const float*)d_in[8];
    const float* hist_W      = (const float*)d_in[9];
    const float* hist_b      = (const float*)d_in[10];
    const float* feat_W      = (const float*)d_in[11];
    const float* feat_b      = (const float*)d_in[12];
    const float* wc_W        = (const float*)d_in[13];
    const float* wc_b        = (const float*)d_in[14];
    const float* W_ih        = (const float*)d_in[15];
    const float* W_hh        = (const float*)d_in[16];
    const float* b_ih        = (const float*)d_in[17];
    const float* b_hh        = (const float*)d_in[18];
    float* out = (float*)d_out;

    prep_weights<<<512, 256>>>(td_h_W, hist_W, feat_W, wc_W, W_ih, W_hh, b_ih, b_hh);
    gammax_kernel<<<(BT * Fsz + 255) / 256, 256>>>(d, td_x_W, td_x_b);
    gammah_gemm<<<dim3(BT / 64, Hsz / 64), 256>>>(d, td_h_b);
    alpha_gemm<<<dim3(BT / 64, Fsz / 64), 256>>>(m, wc_b);
    denom_kernel<<<Tsz, 256>>>(target_mask);
    init_state<<<(Bsz * Hsz + 255) / 256, 256>>>();

    for (int t = 0; t < Tsz; t++) {
        step1_kernel<<<32, 256>>>(x, m, target_x, target_mask, hist_b, feat_b, out, t);
        step2_kernel<<<dim3(8, 32), 256>>>();
    }
    loss_final<<<1, 128>>>(out, out_size);
}

// round 4
// speedup vs baseline: 1.4455x; 1.4455x over previous
#include <cuda_runtime.h>
#include <math.h>

#define Bsz 256
#define Tsz 128
#define Fsz 128
#define Hsz 512
#define BT  (Bsz * Tsz)          // 32768
#define KC  768                  // c_c(128) + h(512) + m(128)
#define N4H 2048                 // 4*H, gate-interleaved

// ----- device scratch (allocation-free rule: __device__ globals) -----
__device__ float g_h[Bsz * Hsz];
__device__ float g_c[Bsz * Hsz];
__device__ float g_xvec[Bsz * KC];                 // per-step [c_c | h_dec | m]
__device__ float g_gamma_h[(size_t)BT * Hsz];      // 64 MB
__device__ float g_gamma_x[BT * Fsz];
__device__ float g_alpha[BT * Fsz];
__device__ float g_inv_denom[Tsz];
__device__ float g_losspart[Tsz * 128];            // per (t, row-pair)
__device__ float g_tdhT[Fsz * Hsz];                // td_h_W transposed [k][n]
__device__ float g_histT[Hsz * Fsz];               // hist_W transposed [k][f]
__device__ float g_featMT[Fsz * Fsz];              // masked feat, [j][f]
__device__ float g_wcT[2 * Fsz * Fsz];             // wc_W transposed [k][n]
__device__ float g_WcombT[KC * N4H];               // gate weights [k][n], gate-interleaved
__device__ float g_bcomb[N4H];

// grid barrier state
__device__ int g_bar_count = 0;
__device__ volatile int g_bar_gen = 0;

// ----------------------------------------------------------------------
// P0: weight transforms
// ----------------------------------------------------------------------
__global__ void prep_weights(const float* __restrict__ td_h_W,
                             const float* __restrict__ hist_W,
                             const float* __restrict__ feat_W,
                             const float* __restrict__ wc_W,
                             const float* __restrict__ W_ih,
                             const float* __restrict__ W_hh,
                             const float* __restrict__ b_ih,
                             const float* __restrict__ b_hh) {
    int stride = gridDim.x * blockDim.x;
    int tid = blockIdx.x * blockDim.x + threadIdx.x;
    for (int i = tid; i < Fsz * Hsz; i += stride) {
        int k = i / Hsz, n = i % Hsz;
        g_tdhT[i] = td_h_W[n * Fsz + k];
    }
    for (int i = tid; i < Hsz * Fsz; i += stride) {
        int k = i / Fsz, f = i % Fsz;
        g_histT[i] = hist_W[f * Hsz + k];
    }
    for (int i = tid; i < Fsz * Fsz; i += stride) {
        int j = i / Fsz, f = i % Fsz;
        g_featMT[i] = (j == f) ? 0.f : feat_W[f * Fsz + j];
    }
    for (int i = tid; i < 2 * Fsz * Fsz; i += stride) {
        int k = i / Fsz, n = i % Fsz;
        g_wcT[i] = wc_W[n * 2 * Fsz + k];
    }
    for (int i = tid; i < KC * N4H; i += stride) {
        int k = i / N4H, n = i % N4H;
        int j = n >> 2, g = n & 3;
        int row = g * Hsz + j;
        float v;
        if (k < Fsz)            v = W_ih[row * (2 * Fsz) + k];
        else if (k < Fsz + Hsz) v = W_hh[row * Hsz + (k - Fsz)];
        else                    v = W_ih[row * (2 * Fsz) + Fsz + (k - Fsz - Hsz)];
        g_WcombT[i] = v;
    }
    for (int i = tid; i < N4H; i += stride) {
        int j = i >> 2, g = i & 3;
        g_bcomb[i] = b_ih[g * Hsz + j] + b_hh[g * Hsz + j];
    }
}

// ----------------------------------------------------------------------
__global__ void gammax_kernel(const float* __restrict__ d,
                              const float* __restrict__ td_x_W,
                              const float* __restrict__ td_x_b) {
    int i = blockIdx.x * blockDim.x + threadIdx.x;
    if (i < BT * Fsz) {
        int f = i & (Fsz - 1);
        float v = d[i] * td_x_W[f * Fsz + f] + td_x_b[f];
        g_gamma_x[i] = expf(-fmaxf(v, 0.f));
    }
}

// ----------------------------------------------------------------------
// gamma_h GEMM: M=BT, N=512, K=128
// ----------------------------------------------------------------------
__global__ void gammah_gemm(const float* __restrict__ d,
                            const float* __restrict__ td_h_b) {
    __shared__ float sA[64][33];
    __shared__ float sB[32][64];
    int m0 = blockIdx.x * 64;
    int n0 = blockIdx.y * 64;
    int tid = threadIdx.x;
    int tx = tid & 15, ty = tid >> 4;
    float acc[4][4] = {};
    for (int kk = 0; kk < Fsz; kk += 32) {
        for (int i = tid; i < 64 * 32; i += 256) {
            int r = i >> 5, k = i & 31;
            sA[r][k] = d[(size_t)(m0 + r) * Fsz + kk + k];
        }
        for (int i = tid; i < 32 * 64; i += 256) {
            int k = i >> 6, n = i & 63;
            sB[k][n] = g_tdhT[(kk + k) * Hsz + n0 + n];
        }
        __syncthreads();
#pragma unroll
        for (int k = 0; k < 32; k++) {
            float a[4], b[4];
#pragma unroll
            for (int i = 0; i < 4; i++) a[i] = sA[ty + i * 16][k];
#pragma unroll
            for (int j = 0; j < 4; j++) b[j] = sB[k][tx + j * 16];
#pragma unroll
            for (int i = 0; i < 4; i++)
#pragma unroll
                for (int j = 0; j < 4; j++) acc[i][j] += a[i] * b[j];
        }
        __syncthreads();
    }
#pragma unroll
    for (int i = 0; i < 4; i++)
#pragma unroll
        for (int j = 0; j < 4; j++) {
            int n = n0 + tx + j * 16;
            int row = m0 + ty + i * 16;
            g_gamma_h[(size_t)row * Hsz + n] = expf(-fmaxf(acc[i][j] + td_h_b[n], 0.f));
        }
}

// ----------------------------------------------------------------------
// alpha GEMM M=BT, N=128, K=256
// ----------------------------------------------------------------------
__global__ void alpha_gemm(const float* __restrict__ m,
                           const float* __restrict__ wc_b) {
    __shared__ float sA[64][33];
    __shared__ float sB[32][64];
    int m0 = blockIdx.x * 64;
    int n0 = blockIdx.y * 64;
    int tid = threadIdx.x;
    int tx = tid & 15, ty = tid >> 4;
    float acc[4][4] = {};
    for (int kk = 0; kk < 2 * Fsz; kk += 32) {
        for (int i = tid; i < 64 * 32; i += 256) {
            int r = i >> 5, k = i & 31;
            int kg = kk + k;
            float v = (kg < Fsz) ? g_gamma_x[(m0 + r) * Fsz + kg]
                                 : m[(size_t)(m0 + r) * Fsz + (kg - Fsz)];
            sA[r][k] = v;
        }
        for (int i = tid; i < 32 * 64; i += 256) {
            int k = i >> 6, n = i & 63;
            sB[k][n] = g_wcT[(kk + k) * Fsz + n0 + n];
        }
        __syncthreads();
#pragma unroll
        for (int k = 0; k < 32; k++) {
            float a[4], b[4];
#pragma unroll
            for (int i = 0; i < 4; i++) a[i] = sA[ty + i * 16][k];
#pragma unroll
            for (int j = 0; j < 4; j++) b[j] = sB[k][tx + j * 16];
#pragma unroll
            for (int i = 0; i < 4; i++)
#pragma unroll
                for (int j = 0; j < 4; j++) acc[i][j] += a[i] * b[j];
        }
        __syncthreads();
    }
#pragma unroll
    for (int i = 0; i < 4; i++)
#pragma unroll
        for (int j = 0; j < 4; j++) {
            int n = n0 + tx + j * 16;
            int row = m0 + ty + i * 16;
            float v = acc[i][j] + wc_b[n];
            g_alpha[row * Fsz + n] = 1.f / (1.f + expf(-v));
        }
}

// ----------------------------------------------------------------------
__global__ void denom_kernel(const float* __restrict__ target_mask) {
    int t = blockIdx.x;
    float s = 0.f;
    for (int i = threadIdx.x; i < Bsz * Fsz; i += blockDim.x) {
        int b = i >> 7, f = i & 127;
        s += target_mask[((size_t)b * Tsz + t) * Fsz + f];
    }
    for (int o = 16; o; o >>= 1) s += __shfl_down_sync(0xffffffffu, s, o);
    __shared__ float red[8];
    if ((threadIdx.x & 31) == 0) red[threadIdx.x >> 5] = s;
    __syncthreads();
    if (threadIdx.x == 0) {
        float tot = 0.f;
        for (int i = 0; i < 8; i++) tot += red[i];
        g_inv_denom[t] = 1.f / (tot + 1e-8f);
    }
}

// ======================================================================
// Persistent recurrence kernel: one wave of gridDim.x==numSMs blocks,
// 128 time steps, software grid barrier (all blocks co-resident).
// ======================================================================
__device__ __forceinline__ void grid_sync(int& gen) {
    __syncthreads();
    if (threadIdx.x == 0) {
        int target = gen + 1;
        __threadfence();
        int a = atomicAdd(&g_bar_count, 1);
        if (a == (int)gridDim.x - 1) {
            g_bar_count = 0;
            __threadfence();
            g_bar_gen = target;
        } else {
            while (g_bar_gen - target < 0) { }
            __threadfence();
        }
    }
    __syncthreads();
    gen++;
}

__global__ void __launch_bounds__(256, 1)
rits_persistent(const float* __restrict__ x,
                const float* __restrict__ m,
                const float* __restrict__ target_x,
                const float* __restrict__ target_mask,
                const float* __restrict__ hist_b,
                const float* __restrict__ feat_b,
                float* __restrict__ out) {
    // shared: phase B needs 64*33 + 32*64 = 4160 floats; phase A aliases front.
    __shared__ float smem[64 * 33 + 32 * 64];
    float* sA  = smem;              // phase B: [64][33]
    float* sB  = smem + 64 * 33;    // phase B: [32][64]
    float* sh  = smem;              // phase A: [2][512]
    float* sxc = smem + 1024;       // phase A: [2][128]
    float* sred = smem + 1280;      // phase A: [8]

    const int tid = threadIdx.x;
    const int bid = blockIdx.x;
    const int G = gridDim.x;

    int gen = g_bar_gen;            // residual base (stable until first release)

    // zero initial state
    for (int i = bid * 256 + tid; i < Bsz * Hsz; i += G * 256) {
        g_h[i] = 0.f; g_c[i] = 0.f;
    }
    grid_sync(gen);

    const int tx = tid & 15, ty = tid >> 4;     // phase B mapping
    const int rr = tid >> 7, f = tid & 127;     // phase A mapping

    for (int t = 0; t < Tsz; t++) {
        // ---------------- Phase A: per-row decay/hist/feat/combine/loss ----------------
        for (int p = bid; p < Bsz / 2; p += G) {
            // h_dec for both rows of the pair
            for (int i = tid; i < 1024; i += 256) {
                int r2 = i >> 9, k = i & 511;
                int r = 2 * p + r2;
                float hv = g_h[r * Hsz + k] *
                           g_gamma_h[((size_t)r * Tsz + t) * Hsz + k];
                sh[i] = hv;
                g_xvec[r * KC + Fsz + k] = hv;
            }
            __syncthreads();

            int r = 2 * p + rr;
            size_t base = ((size_t)r * Tsz + t) * Fsz + f;

            float acc = 0.f;
#pragma unroll 8
            for (int k = 0; k < Hsz; k++)
                acc += sh[rr * Hsz + k] * g_histT[k * Fsz + f];
            float xh = acc + hist_b[f];
            float mv = m[base];
            float xv = x[base];
            float xc = mv * xv + (1.f - mv) * xh;
            sxc[rr * Fsz + f] = xc;
            g_xvec[r * KC + (Fsz + Hsz) + f] = mv;
            __syncthreads();

            float accz = 0.f;
#pragma unroll 8
            for (int j = 0; j < Fsz; j++)
                accz += sxc[rr * Fsz + j] * g_featMT[j * Fsz + f];
            float z = accz + feat_b[f];
            float a = g_alpha[base];
            float ch = a * z + (1.f - a) * xh;
            float cc = mv * xv + (1.f - mv) * ch;
            g_xvec[r * KC + f] = cc;
            out[base] = cc;

            float ev = target_mask[base];
            float tg = target_x[base];
            float d1 = xh - tg, d2 = z - tg, d3 = ch - tg;
            float lp = ev * (d1 * d1 + d2 * d2 + d3 * d3);
            for (int o = 16; o; o >>= 1) lp += __shfl_down_sync(0xffffffffu, lp, o);
            if ((tid & 31) == 0) sred[tid >> 5] = lp;
            __syncthreads();
            if (tid == 0) {
                float tot = 0.f;
                for (int i = 0; i < 8; i++) tot += sred[i];
                g_losspart[t * 128 + p] = tot;
            }
            __syncthreads();
        }
        grid_sync(gen);

        // ---------------- Phase B: gate GEMM 256x2048xK768 + LSTM epilogue ----------------
        // 128 tiles of 64 rows x 64 gate-cols; one tile per block.
        for (int tile = bid; tile < 128; tile += G) {
            int b0 = (tile >> 5) * 64;          // 4 row-tiles
            int n0 = (tile & 31) * 64;          // 32 n-tiles
            float acc[4][4] = {};
            for (int kk = 0; kk < KC; kk += 32) {
                for (int i = tid; i < 64 * 32; i += 256) {
                    int r2 = i >> 5, k = i & 31;
                    sA[r2 * 33 + k] = g_xvec[(b0 + r2) * KC + kk + k];
                }
                for (int i = tid; i < 32 * 64; i += 256) {
                    int k = i >> 6, n = i & 63;
                    sB[k * 64 + n] = g_WcombT[(kk + k) * N4H + n0 + n];
                }
                __syncthreads();
#pragma unroll
                for (int k = 0; k < 32; k++) {
                    float av[4];
#pragma unroll
                    for (int i = 0; i < 4; i++) av[i] = sA[(ty + i * 16) * 33 + k];
                    float4 bv = *reinterpret_cast<float4*>(&sB[k * 64 + tx * 4]);
#pragma unroll
                    for (int i = 0; i < 4; i++) {
                        acc[i][0] += av[i] * bv.x;
                        acc[i][1] += av[i] * bv.y;
                        acc[i][2] += av[i] * bv.z;
                        acc[i][3] += av[i] * bv.w;
                    }
                }
                __syncthreads();
            }
            int j = (n0 >> 2) + tx;
            float bi = g_bcomb[n0 + tx * 4 + 0];
            float bf = g_bcomb[n0 + tx * 4 + 1];
            float bg = g_bcomb[n0 + tx * 4 + 2];
            float bo = g_bcomb[n0 + tx * 4 + 3];
#pragma unroll
            for (int i = 0; i < 4; i++) {
                int b = b0 + ty + i * 16;
                float gi = acc[i][0] + bi;
                float gf = acc[i][1] + bf;
                float gg = acc[i][2] + bg;
                float go = acc[i][3] + bo;
                float si = 1.f / (1.f + expf(-gi));
                float sf = 1.f / (1.f + expf(-gf));
                float so = 1.f / (1.f + expf(-go));
                float tg = tanhf(gg);
                float cn = sf * g_c[b * Hsz + j] + si * tg;
                g_c[b * Hsz + j] = cn;
                g_h[b * Hsz + j] = so * tanhf(cn);
            }
        }
        grid_sync(gen);
    }
}

// ----------------------------------------------------------------------
__global__ void loss_final(float* __restrict__ out, int out_size) {
    __shared__ float s[128];
    int t = threadIdx.x;
    float v = 0.f;
    for (int p = 0; p < 128; p++) v += g_losspart[t * 128 + p];
    s[t] = v * g_inv_denom[t];
    __syncthreads();
    if (t == 0) {
        float tot = 0.f;
        for (int i = 0; i < 128; i++) tot += s[i];
        out[out_size - 1] = tot / (float)Tsz;
    }
}

// ----------------------------------------------------------------------
extern "C" void kernel_launch(void* const* d_in, const int* in_sizes, int n_in,
                              void* d_out, int out_size) {
    const float* x           = (const float*)d_in[0];
    const float* m           = (const float*)d_in[1];
    const float* d           = (const float*)d_in[2];
    const float* target_x    = (const float*)d_in[3];
    const float* target_mask = (const float*)d_in[4];
    const float* td_h_W      = (const float*)d_in[5];
    const float* td_h_b      = (const float*)d_in[6];
    const float* td_x_W      = (const float*)d_in[7];
    const float* td_x_b      = (const float*)d_in[8];
    const float* hist_W      = (const float*)d_in[9];
    const float* hist_b      = (const float*)d_in[10];
    const float* feat_W      = (const float*)d_in[11];
    const float* feat_b      = (const float*)d_in[12];
    const float* wc_W        = (const float*)d_in[13];
    const float* wc_b        = (const float*)d_in[14];
    const float* W_ih        = (const float*)d_in[15];
    const float* W_hh        = (const float*)d_in[16];
    const float* b_ih        = (const float*)d_in[17];
    const float* b_hh        = (const float*)d_in[18];
    float* out = (float*)d_out;

    int dev = 0, nsm = 148;
    cudaGetDevice(&dev);
    cudaDeviceGetAttribute(&nsm, cudaDevAttrMultiProcessorCount, dev);
    if (nsm > 512) nsm = 512;

    prep_weights<<<512, 256>>>(td_h_W, hist_W, feat_W, wc_W, W_ih, W_hh, b_ih, b_hh);
    gammax_kernel<<<(BT * Fsz + 255) / 256, 256>>>(d, td_x_W, td_x_b);
    gammah_gemm<<<dim3(BT / 64, Hsz / 64), 256>>>(d, td_h_b);
    alpha_gemm<<<dim3(BT / 64, Fsz / 64), 256>>>(m, wc_b);
    denom_kernel<<<Tsz, 256>>>(target_mask);

    rits_persistent<<<nsm, 256>>>(x, m, target_x, target_mask, hist_b, feat_b, out);

    loss_final<<<1, 128>>>(out, out_size);
}

// round 5
// speedup vs baseline: 1.8445x; 1.2760x over previous
#include <cuda_runtime.h>
#include <math.h>

#define Bsz 256
#define Tsz 128
#define Fsz 128
#define Hsz 512
#define BT  (Bsz * Tsz)          // 32768
#define KC  768                  // c_c(128) + h(512) + m(128)
#define N4H 2048                 // 4*H, gate-interleaved
#define NBLK 128                 // persistent grid size

// ----- device scratch (allocation-free rule: __device__ globals) -----
__device__ float g_h[Bsz * Hsz];
__device__ float g_c[Bsz * Hsz];
__device__ float g_xvec[Bsz * KC];                 // per-step [c_c | h_dec | m]
__device__ float g_gamma_h[(size_t)BT * Hsz];      // 64 MB
__device__ float g_gamma_x[BT * Fsz];
__device__ float g_alpha[BT * Fsz];
__device__ float g_inv_denom[Tsz];
__device__ float g_losspart[Tsz * 128];
__device__ float g_tdhT[Fsz * Hsz];
__device__ float g_histT[Hsz * Fsz];
__device__ float g_featMT[Fsz * Fsz];
__device__ float g_wcT[2 * Fsz * Fsz];
__device__ float g_WcombT[KC * N4H];               // [k][n], gate-interleaved
__device__ float g_bcomb[N4H];
__device__ float g_part[(size_t)32 * 4 * 128 * 128];   // split-K partials, 8MB
__device__ int   g_tilecnt[32];

// grid barrier state
__device__ int g_bar_count = 0;
__device__ volatile int g_bar_gen = 0;

// ----------------------------------------------------------------------
__global__ void prep_weights(const float* __restrict__ td_h_W,
                             const float* __restrict__ hist_W,
                             const float* __restrict__ feat_W,
                             const float* __restrict__ wc_W,
                             const float* __restrict__ W_ih,
                             const float* __restrict__ W_hh,
                             const float* __restrict__ b_ih,
                             const float* __restrict__ b_hh) {
    int stride = gridDim.x * blockDim.x;
    int tid = blockIdx.x * blockDim.x + threadIdx.x;
    for (int i = tid; i < Fsz * Hsz; i += stride) {
        int k = i / Hsz, n = i % Hsz;
        g_tdhT[i] = td_h_W[n * Fsz + k];
    }
    for (int i = tid; i < Hsz * Fsz; i += stride) {
        int k = i / Fsz, f = i % Fsz;
        g_histT[i] = hist_W[f * Hsz + k];
    }
    for (int i = tid; i < Fsz * Fsz; i += stride) {
        int j = i / Fsz, f = i % Fsz;
        g_featMT[i] = (j == f) ? 0.f : feat_W[f * Fsz + j];
    }
    for (int i = tid; i < 2 * Fsz * Fsz; i += stride) {
        int k = i / Fsz, n = i % Fsz;
        g_wcT[i] = wc_W[n * 2 * Fsz + k];
    }
    for (int i = tid; i < KC * N4H; i += stride) {
        int k = i / N4H, n = i % N4H;
        int j = n >> 2, g = n & 3;
        int row = g * Hsz + j;
        float v;
        if (k < Fsz)            v = W_ih[row * (2 * Fsz) + k];
        else if (k < Fsz + Hsz) v = W_hh[row * Hsz + (k - Fsz)];
        else                    v = W_ih[row * (2 * Fsz) + Fsz + (k - Fsz - Hsz)];
        g_WcombT[i] = v;
    }
    for (int i = tid; i < N4H; i += stride) {
        int j = i >> 2, g = i & 3;
        g_bcomb[i] = b_ih[g * Hsz + j] + b_hh[g * Hsz + j];
    }
}

// ----------------------------------------------------------------------
__global__ void gammax_kernel(const float* __restrict__ d,
                              const float* __restrict__ td_x_W,
                              const float* __restrict__ td_x_b) {
    int i = blockIdx.x * blockDim.x + threadIdx.x;
    if (i < BT * Fsz) {
        int f = i & (Fsz - 1);
        float v = d[i] * td_x_W[f * Fsz + f] + td_x_b[f];
        g_gamma_x[i] = expf(-fmaxf(v, 0.f));
    }
}

// ----------------------------------------------------------------------
__global__ void gammah_gemm(const float* __restrict__ d,
                            const float* __restrict__ td_h_b) {
    __shared__ float sA[64][33];
    __shared__ float sB[32][64];
    int m0 = blockIdx.x * 64;
    int n0 = blockIdx.y * 64;
    int tid = threadIdx.x;
    int tx = tid & 15, ty = tid >> 4;
    float acc[4][4] = {};
    for (int kk = 0; kk < Fsz; kk += 32) {
        for (int i = tid; i < 64 * 32; i += 256) {
            int r = i >> 5, k = i & 31;
            sA[r][k] = d[(size_t)(m0 + r) * Fsz + kk + k];
        }
        for (int i = tid; i < 32 * 64; i += 256) {
            int k = i >> 6, n = i & 63;
            sB[k][n] = g_tdhT[(kk + k) * Hsz + n0 + n];
        }
        __syncthreads();
#pragma unroll
        for (int k = 0; k < 32; k++) {
            float a[4], b[4];
#pragma unroll
            for (int i = 0; i < 4; i++) a[i] = sA[ty + i * 16][k];
#pragma unroll
            for (int j = 0; j < 4; j++) b[j] = sB[k][tx + j * 16];
#pragma unroll
            for (int i = 0; i < 4; i++)
#pragma unroll
                for (int j = 0; j < 4; j++) acc[i][j] += a[i] * b[j];
        }
        __syncthreads();
    }
#pragma unroll
    for (int i = 0; i < 4; i++)
#pragma unroll
        for (int j = 0; j < 4; j++) {
            int n = n0 + tx + j * 16;
            int row = m0 + ty + i * 16;
            g_gamma_h[(size_t)row * Hsz + n] = expf(-fmaxf(acc[i][j] + td_h_b[n], 0.f));
        }
}

// ----------------------------------------------------------------------
__global__ void alpha_gemm(const float* __restrict__ m,
                           const float* __restrict__ wc_b) {
    __shared__ float sA[64][33];
    __shared__ float sB[32][64];
    int m0 = blockIdx.x * 64;
    int n0 = blockIdx.y * 64;
    int tid = threadIdx.x;
    int tx = tid & 15, ty = tid >> 4;
    float acc[4][4] = {};
    for (int kk = 0; kk < 2 * Fsz; kk += 32) {
        for (int i = tid; i < 64 * 32; i += 256) {
            int r = i >> 5, k = i & 31;
            int kg = kk + k;
            float v = (kg < Fsz) ? g_gamma_x[(m0 + r) * Fsz + kg]
                                 : m[(size_t)(m0 + r) * Fsz + (kg - Fsz)];
            sA[r][k] = v;
        }
        for (int i = tid; i < 32 * 64; i += 256) {
            int k = i >> 6, n = i & 63;
            sB[k][n] = g_wcT[(kk + k) * Fsz + n0 + n];
        }
        __syncthreads();
#pragma unroll
        for (int k = 0; k < 32; k++) {
            float a[4], b[4];
#pragma unroll
            for (int i = 0; i < 4; i++) a[i] = sA[ty + i * 16][k];
#pragma unroll
            for (int j = 0; j < 4; j++) b[j] = sB[k][tx + j * 16];
#pragma unroll
            for (int i = 0; i < 4; i++)
#pragma unroll
                for (int j = 0; j < 4; j++) acc[i][j] += a[i] * b[j];
        }
        __syncthreads();
    }
#pragma unroll
    for (int i = 0; i < 4; i++)
#pragma unroll
        for (int j = 0; j < 4; j++) {
            int n = n0 + tx + j * 16;
            int row = m0 + ty + i * 16;
            float v = acc[i][j] + wc_b[n];
            g_alpha[row * Fsz + n] = 1.f / (1.f + expf(-v));
        }
}

// ----------------------------------------------------------------------
__global__ void denom_kernel(const float* __restrict__ target_mask) {
    int t = blockIdx.x;
    float s = 0.f;
    for (int i = threadIdx.x; i < Bsz * Fsz; i += blockDim.x) {
        int b = i >> 7, f = i & 127;
        s += target_mask[((size_t)b * Tsz + t) * Fsz + f];
    }
    for (int o = 16; o; o >>= 1) s += __shfl_down_sync(0xffffffffu, s, o);
    __shared__ float red[8];
    if ((threadIdx.x & 31) == 0) red[threadIdx.x >> 5] = s;
    __syncthreads();
    if (threadIdx.x == 0) {
        float tot = 0.f;
        for (int i = 0; i < 8; i++) tot += red[i];
        g_inv_denom[t] = 1.f / (tot + 1e-8f);
    }
}

// ======================================================================
// Persistent recurrence kernel
// ======================================================================
__device__ __forceinline__ void grid_sync(int& gen) {
    __syncthreads();
    if (threadIdx.x == 0) {
        int target = gen + 1;
        __threadfence();
        int a = atomicAdd(&g_bar_count, 1);
        if (a == (int)gridDim.x - 1) {
            g_bar_count = 0;
            __threadfence();
            g_bar_gen = target;
        } else {
            while (g_bar_gen - target < 0) { }
            __threadfence();
        }
    }
    __syncthreads();
    gen++;
}

#define FMA2(acc, a2, b2) \
    asm("fma.rn.f32x2 %0, %1, %2, %0;" : "+l"(acc) : "l"(a2), "l"(b2))
#define DUP32(d, s) \
    asm("mov.b64 %0, {%1, %1};" : "=l"(d) : "r"(s))

__global__ void __launch_bounds__(256, 1)
rits_persistent(const float* __restrict__ x,
                const float* __restrict__ m,
                const float* __restrict__ target_x,
                const float* __restrict__ target_mask,
                const float* __restrict__ hist_b,
                const float* __restrict__ feat_b,
                float* __restrict__ out) {
    // phase B: sA[128][33] (4224) + sB[32][132] (4224) = 8448 floats (33.8KB)
    // phase A aliases the front: sh[2][512], sxc[2][128], sred[8]
    __shared__ float smem[8448];
    __shared__ int s_last;
    float* sA  = smem;
    float* sB  = smem + 4224;
    float* sh  = smem;
    float* sxc = smem + 1024;
    float* sred = smem + 1280;

    const int tid = threadIdx.x;
    const int bid = blockIdx.x;

    int gen = g_bar_gen;

    // init state
    for (int i = bid * 256 + tid; i < Bsz * Hsz; i += NBLK * 256) {
        g_h[i] = 0.f; g_c[i] = 0.f;
    }
    if (bid == 0 && tid < 32) g_tilecnt[tid] = 0;
    grid_sync(gen);

    // phase B decode: bid -> (tile, ks)
    const int ks   = bid & 3;            // K-split 0..3 (K range 192 each)
    const int tile = bid >> 2;           // 0..31
    const int tm   = tile >> 4;          // 0..1 (row half)
    const int tn   = tile & 15;          // 0..15 (128 gate cols)
    const int b0B  = tm * 128;
    const int n0   = tn * 128;
    const int k0b  = ks * 192;
    const int tx = tid & 15, ty = tid >> 4;   // 8x8 micro mapping
    const int rr = tid >> 7, f = tid & 127;   // phase A mapping

#pragma unroll 1
    for (int t = 0; t < Tsz; t++) {
        // ================= Phase A: rows 2*bid, 2*bid+1 =================
        {
            const int p = bid;
            for (int i = tid; i < 1024; i += 256) {
                int r2 = i >> 9, k = i & 511;
                int r = 2 * p + r2;
                float hv = g_h[r * Hsz + k] *
                           g_gamma_h[((size_t)r * Tsz + t) * Hsz + k];
                sh[i] = hv;
                g_xvec[r * KC + Fsz + k] = hv;
            }
            __syncthreads();

            int r = 2 * p + rr;
            size_t base = ((size_t)r * Tsz + t) * Fsz + f;
            const float* shrow = sh + rr * 512;

            float a0 = 0.f, a1 = 0.f, a2 = 0.f, a3 = 0.f;
#pragma unroll 4
            for (int k = 0; k < Hsz; k += 4) {
                a0 += shrow[k]     * g_histT[(k)     * Fsz + f];
                a1 += shrow[k + 1] * g_histT[(k + 1) * Fsz + f];
                a2 += shrow[k + 2] * g_histT[(k + 2) * Fsz + f];
                a3 += shrow[k + 3] * g_histT[(k + 3) * Fsz + f];
            }
            float xh = ((a0 + a1) + (a2 + a3)) + hist_b[f];
            float mv = m[base];
            float xv = x[base];
            float xc = mv * xv + (1.f - mv) * xh;
            sxc[rr * Fsz + f] = xc;
            g_xvec[r * KC + (Fsz + Hsz) + f] = mv;
            __syncthreads();

            float z0 = 0.f, z1 = 0.f, z2 = 0.f, z3 = 0.f;
#pragma unroll 4
            for (int j = 0; j < Fsz; j += 4) {
                z0 += sxc[rr * Fsz + j]     * g_featMT[(j)     * Fsz + f];
                z1 += sxc[rr * Fsz + j + 1] * g_featMT[(j + 1) * Fsz + f];
                z2 += sxc[rr * Fsz + j + 2] * g_featMT[(j + 2) * Fsz + f];
                z3 += sxc[rr * Fsz + j + 3] * g_featMT[(j + 3) * Fsz + f];
            }
            float z = ((z0 + z1) + (z2 + z3)) + feat_b[f];
            float a = g_alpha[base];
            float ch = a * z + (1.f - a) * xh;
            float cc = mv * xv + (1.f - mv) * ch;
            g_xvec[r * KC + f] = cc;
            out[base] = cc;

            float ev = target_mask[base];
            float tg = target_x[base];
            float d1 = xh - tg, d2 = z - tg, d3 = ch - tg;
            float lp = ev * (d1 * d1 + d2 * d2 + d3 * d3);
            for (int o = 16; o; o >>= 1) lp += __shfl_down_sync(0xffffffffu, lp, o);
            if ((tid & 31) == 0) sred[tid >> 5] = lp;
            __syncthreads();
            if (tid == 0) {
                float tot = 0.f;
                for (int i = 0; i < 8; i++) tot += sred[i];
                g_losspart[t * 128 + p] = tot;
            }
        }
        grid_sync(gen);

        // ================= Phase B: split-K gate GEMM 128x128x192 =================
        {
            unsigned long long acc[8][4];
#pragma unroll
            for (int i = 0; i < 8; i++)
#pragma unroll
                for (int j = 0; j < 4; j++) acc[i][j] = 0ull;

#pragma unroll 1
            for (int kb = 0; kb < 6; kb++) {
                const int k0 = k0b + kb * 32;
                __syncthreads();
                // sA[m][k]: 128 rows x 32 k  (scalar stores, conflict-free)
                for (int i = tid; i < 1024; i += 256) {
                    int mm = i >> 3, kq = i & 7;
                    float4 v = *reinterpret_cast<const float4*>(
                        &g_xvec[(b0B + mm) * KC + k0 + kq * 4]);
                    float* dst = &sA[mm * 33 + kq * 4];
                    dst[0] = v.x; dst[1] = v.y; dst[2] = v.z; dst[3] = v.w;
                }
                // sB[k][n]: 32 k x 128 n  (float4 stores)
                for (int i = tid; i < 1024; i += 256) {
                    int kk = i >> 5, nq = i & 31;
                    float4 v = *reinterpret_cast<const float4*>(
                        &g_WcombT[(size_t)(k0 + kk) * N4H + n0 + nq * 4]);
                    *reinterpret_cast<float4*>(&sB[kk * 132 + nq * 4]) = v;
                }
                __syncthreads();

#pragma unroll 8
                for (int k = 0; k < 32; k++) {
                    const unsigned* arow = reinterpret_cast<const unsigned*>(sA) + k;
                    unsigned long long ad[8];
#pragma unroll
                    for (int r2 = 0; r2 < 8; r2++) {
                        unsigned av = arow[(ty * 8 + r2) * 33];
                        DUP32(ad[r2], av);
                    }
                    ulonglong2 bb0 = *reinterpret_cast<const ulonglong2*>(
                        &sB[k * 132 + tx * 8]);
                    ulonglong2 bb1 = *reinterpret_cast<const ulonglong2*>(
                        &sB[k * 132 + tx * 8 + 4]);
#pragma unroll
                    for (int r2 = 0; r2 < 8; r2++) {
                        FMA2(acc[r2][0], ad[r2], bb0.x);
                        FMA2(acc[r2][1], ad[r2], bb0.y);
                        FMA2(acc[r2][2], ad[r2], bb1.x);
                        FMA2(acc[r2][3], ad[r2], bb1.y);
                    }
                }
            }

            // store partials (packed 64-bit stores)
            size_t pbase = (size_t)(tile * 4 + ks) * 16384;
#pragma unroll
            for (int r2 = 0; r2 < 8; r2++) {
#pragma unroll
                for (int cp = 0; cp < 4; cp++) {
                    size_t off = pbase + (size_t)(ty * 8 + r2) * 128 + tx * 8 + cp * 2;
                    *reinterpret_cast<unsigned long long*>(&g_part[off]) = acc[r2][cp];
                }
            }
            __threadfence();
            __syncthreads();
            if (tid == 0) {
                int old = atomicAdd(&g_tilecnt[tile], 1);
                s_last = (old == 3);
            }
            __syncthreads();
            if (s_last) {
                __threadfence();   // acquire partials of the other 3 blocks
                size_t tb = (size_t)tile * 4 * 16384;
                for (int idx = tid; idx < 4096; idx += 256) {
                    int row = idx >> 5, u = idx & 31;
                    size_t go_off = (size_t)row * 128 + u * 4;
                    float4 p0 = *reinterpret_cast<const float4*>(&g_part[tb + go_off]);
                    float4 p1 = *reinterpret_cast<const float4*>(&g_part[tb + 16384 + go_off]);
                    float4 p2 = *reinterpret_cast<const float4*>(&g_part[tb + 32768 + go_off]);
                    float4 p3 = *reinterpret_cast<const float4*>(&g_part[tb + 49152 + go_off]);
                    float gi = ((p0.x + p1.x) + (p2.x + p3.x)) + g_bcomb[n0 + u * 4 + 0];
                    float gf = ((p0.y + p1.y) + (p2.y + p3.y)) + g_bcomb[n0 + u * 4 + 1];
                    float gg = ((p0.z + p1.z) + (p2.z + p3.z)) + g_bcomb[n0 + u * 4 + 2];
                    float gO = ((p0.w + p1.w) + (p2.w + p3.w)) + g_bcomb[n0 + u * 4 + 3];
                    float si = 1.f / (1.f + expf(-gi));
                    float sf = 1.f / (1.f + expf(-gf));
                    float so = 1.f / (1.f + expf(-gO));
                    float tg = tanhf(gg);
                    int b = b0B + row;
                    int j = (n0 >> 2) + u;
                    float cn = sf * g_c[b * Hsz + j] + si * tg;
                    g_c[b * Hsz + j] = cn;
                    g_h[b * Hsz + j] = so * tanhf(cn);
                }
                __syncthreads();
                if (tid == 0) g_tilecnt[tile] = 0;
            }
        }
        grid_sync(gen);
    }
}

// ----------------------------------------------------------------------
__global__ void loss_final(float* __restrict__ out, int out_size) {
    __shared__ float s[128];
    int t = threadIdx.x;
    float v = 0.f;
    for (int p = 0; p < 128; p++) v += g_losspart[t * 128 + p];
    s[t] = v * g_inv_denom[t];
    __syncthreads();
    if (t == 0) {
        float tot = 0.f;
        for (int i = 0; i < 128; i++) tot += s[i];
        out[out_size - 1] = tot / (float)Tsz;
    }
}

// ----------------------------------------------------------------------
extern "C" void kernel_launch(void* const* d_in, const int* in_sizes, int n_in,
                              void* d_out, int out_size) {
    const float* x           = (const float*)d_in[0];
    const float* m           = (const float*)d_in[1];
    const float* d           = (const float*)d_in[2];
    const float* target_x    = (const float*)d_in[3];
    const float* target_mask = (const float*)d_in[4];
    const float* td_h_W      = (const float*)d_in[5];
    const float* td_h_b      = (const float*)d_in[6];
    const float* td_x_W      = (const float*)d_in[7];
    const float* td_x_b      = (const float*)d_in[8];
    const float* hist_W      = (const float*)d_in[9];
    const float* hist_b      = (const float*)d_in[10];
    const float* feat_W      = (const float*)d_in[11];
    const float* feat_b      = (const float*)d_in[12];
    const float* wc_W        = (const float*)d_in[13];
    const float* wc_b        = (const float*)d_in[14];
    const float* W_ih        = (const float*)d_in[15];
    const float* W_hh        = (const float*)d_in[16];
    const float* b_ih        = (const float*)d_in[17];
    const float* b_hh        = (const float*)d_in[18];
    float* out = (float*)d_out;

    prep_weights<<<512, 256>>>(td_h_W, hist_W, feat_W, wc_W, W_ih, W_hh, b_ih, b_hh);
    gammax_kernel<<<(BT * Fsz + 255) / 256, 256>>>(d, td_x_W, td_x_b);
    gammah_gemm<<<dim3(BT / 64, Hsz / 64), 256>>>(d, td_h_b);
    alpha_gemm<<<dim3(BT / 64, Fsz / 64), 256>>>(m, wc_b);
    denom_kernel<<<Tsz, 256>>>(target_mask);

    rits_persistent<<<NBLK, 256>>>(x, m, target_x, target_mask, hist_b, feat_b, out);

    loss_final<<<1, 128>>>(out, out_size);
}

// round 7
// speedup vs baseline: 2.0304x; 1.1008x over previous
#include <cuda_runtime.h>
#include <math.h>

#define Bsz 256
#define Tsz 128
#define Fsz 128
#define Hsz 512
#define BT  (Bsz * Tsz)          // 32768
#define KC  768                  // c_c(128) + h_dec(512) + m(128)
#define N4H 2048                 // 4*H, gate-interleaved
#define NBLK 128                 // persistent grid size

typedef unsigned long long ull;

// ----- device scratch (allocation-free rule: __device__ globals) -----
__device__ __align__(16) float g_h[Bsz * Hsz];
__device__ __align__(16) float g_c[Bsz * Hsz];
__device__ __align__(16) float g_xvec[Bsz * KC];
__device__ __align__(16) float g_xhist[Bsz * Fsz];
__device__ __align__(16) float g_gamma_h[(size_t)BT * Hsz];   // 64 MB
__device__ __align__(16) float g_gamma_x[BT * Fsz];
__device__ __align__(16) float g_alpha[BT * Fsz];
__device__ float g_inv_denom[Tsz];
__device__ float g_losspart[Tsz * 128];
__device__ __align__(16) float g_tdhT[Fsz * Hsz];
__device__ __align__(16) float g_histT[Hsz * Fsz];
__device__ __align__(16) float g_featMT[Fsz * Fsz];
__device__ __align__(16) float g_wcT[2 * Fsz * Fsz];
__device__ __align__(16) float g_WcombT[KC * N4H];
__device__ __align__(16) float g_bcomb[N4H];
__device__ __align__(16) float g_part[(size_t)32 * 4 * 128 * 128];  // P4 split-K partials
__device__ __align__(16) float g_p1part[32 * 4 * 1024];             // P1 split-K partials
__device__ int g_tilecnt[32];
__device__ int g_cnt1[32];

// flag-array grid barrier
__device__ volatile int g_arrive[NBLK];
__device__ volatile int g_release;

// ----------------------------------------------------------------------
__global__ void prep_weights(const float* __restrict__ td_h_W,
                             const float* __restrict__ hist_W,
                             const float* __restrict__ feat_W,
                             const float* __restrict__ wc_W,
                             const float* __restrict__ W_ih,
                             const float* __restrict__ W_hh,
                             const float* __restrict__ b_ih,
                             const float* __restrict__ b_hh) {
    int stride = gridDim.x * blockDim.x;
    int tid = blockIdx.x * blockDim.x + threadIdx.x;
    for (int i = tid; i < Fsz * Hsz; i += stride) {
        int k = i / Hsz, n = i % Hsz;
        g_tdhT[i] = td_h_W[n * Fsz + k];
    }
    for (int i = tid; i < Hsz * Fsz; i += stride) {
        int k = i / Fsz, f = i % Fsz;
        g_histT[i] = hist_W[f * Hsz + k];
    }
    for (int i = tid; i < Fsz * Fsz; i += stride) {
        int j = i / Fsz, f = i % Fsz;
        g_featMT[i] = (j == f) ? 0.f : feat_W[f * Fsz + j];
    }
    for (int i = tid; i < 2 * Fsz * Fsz; i += stride) {
        int k = i / Fsz, n = i % Fsz;
        g_wcT[i] = wc_W[n * 2 * Fsz + k];
    }
    for (int i = tid; i < KC * N4H; i += stride) {
        int k = i / N4H, n = i % N4H;
        int j = n >> 2, g = n & 3;
        int row = g * Hsz + j;
        float v;
        if (k < Fsz)            v = W_ih[row * (2 * Fsz) + k];
        else if (k < Fsz + Hsz) v = W_hh[row * Hsz + (k - Fsz)];
        else                    v = W_ih[row * (2 * Fsz) + Fsz + (k - Fsz - Hsz)];
        g_WcombT[i] = v;
    }
    for (int i = tid; i < N4H; i += stride) {
        int j = i >> 2, g = i & 3;
        g_bcomb[i] = b_ih[g * Hsz + j] + b_hh[g * Hsz + j];
    }
}

// ----------------------------------------------------------------------
__global__ void gammax_kernel(const float* __restrict__ d,
                              const float* __restrict__ td_x_W,
                              const float* __restrict__ td_x_b) {
    int i = blockIdx.x * blockDim.x + threadIdx.x;
    if (i < BT * Fsz) {
        int f = i & (Fsz - 1);
        float v = d[i] * td_x_W[f * Fsz + f] + td_x_b[f];
        g_gamma_x[i] = expf(-fmaxf(v, 0.f));
    }
}

// ----------------------------------------------------------------------
__global__ void gammah_gemm(const float* __restrict__ d,
                            const float* __restrict__ td_h_b) {
    __shared__ float sA[64][33];
    __shared__ float sB[32][64];
    int m0 = blockIdx.x * 64;
    int n0 = blockIdx.y * 64;
    int tid = threadIdx.x;
    int tx = tid & 15, ty = tid >> 4;
    float acc[4][4] = {};
    for (int kk = 0; kk < Fsz; kk += 32) {
        for (int i = tid; i < 64 * 32; i += 256) {
            int r = i >> 5, k = i & 31;
            sA[r][k] = d[(size_t)(m0 + r) * Fsz + kk + k];
        }
        for (int i = tid; i < 32 * 64; i += 256) {
            int k = i >> 6, n = i & 63;
            sB[k][n] = g_tdhT[(kk + k) * Hsz + n0 + n];
        }
        __syncthreads();
#pragma unroll
        for (int k = 0; k < 32; k++) {
            float a[4], b[4];
#pragma unroll
            for (int i = 0; i < 4; i++) a[i] = sA[ty + i * 16][k];
#pragma unroll
            for (int j = 0; j < 4; j++) b[j] = sB[k][tx + j * 16];
#pragma unroll
            for (int i = 0; i < 4; i++)
#pragma unroll
                for (int j = 0; j < 4; j++) acc[i][j] += a[i] * b[j];
        }
        __syncthreads();
    }
#pragma unroll
    for (int i = 0; i < 4; i++)
#pragma unroll
        for (int j = 0; j < 4; j++) {
            int n = n0 + tx + j * 16;
            int row = m0 + ty + i * 16;
            g_gamma_h[(size_t)row * Hsz + n] = expf(-fmaxf(acc[i][j] + td_h_b[n], 0.f));
        }
}

// ----------------------------------------------------------------------
__global__ void alpha_gemm(const float* __restrict__ m,
                           const float* __restrict__ wc_b) {
    __shared__ float sA[64][33];
    __shared__ float sB[32][64];
    int m0 = blockIdx.x * 64;
    int n0 = blockIdx.y * 64;
    int tid = threadIdx.x;
    int tx = tid & 15, ty = tid >> 4;
    float acc[4][4] = {};
    for (int kk = 0; kk < 2 * Fsz; kk += 32) {
        for (int i = tid; i < 64 * 32; i += 256) {
            int r = i >> 5, k = i & 31;
            int kg = kk + k;
            float v = (kg < Fsz) ? g_gamma_x[(m0 + r) * Fsz + kg]
                                 : m[(size_t)(m0 + r) * Fsz + (kg - Fsz)];
            sA[r][k] = v;
        }
        for (int i = tid; i < 32 * 64; i += 256) {
            int k = i >> 6, n = i & 63;
            sB[k][n] = g_wcT[(kk + k) * Fsz + n0 + n];
        }
        __syncthreads();
#pragma unroll
        for (int k = 0; k < 32; k++) {
            float a[4], b[4];
#pragma unroll
            for (int i = 0; i < 4; i++) a[i] = sA[ty + i * 16][k];
#pragma unroll
            for (int j = 0; j < 4; j++) b[j] = sB[k][tx + j * 16];
#pragma unroll
            for (int i = 0; i < 4; i++)
#pragma unroll
                for (int j = 0; j < 4; j++) acc[i][j] += a[i] * b[j];
        }
        __syncthreads();
    }
#pragma unroll
    for (int i = 0; i < 4; i++)
#pragma unroll
        for (int j = 0; j < 4; j++) {
            int n = n0 + tx + j * 16;
            int row = m0 + ty + i * 16;
            float v = acc[i][j] + wc_b[n];
            g_alpha[row * Fsz + n] = 1.f / (1.f + expf(-v));
        }
}

// ----------------------------------------------------------------------
__global__ void denom_kernel(const float* __restrict__ target_mask) {
    int t = blockIdx.x;
    float s = 0.f;
    for (int i = threadIdx.x; i < Bsz * Fsz; i += blockDim.x) {
        int b = i >> 7, f = i & 127;
        s += target_mask[((size_t)b * Tsz + t) * Fsz + f];
    }
    for (int o = 16; o; o >>= 1) s += __shfl_down_sync(0xffffffffu, s, o);
    __shared__ float red[8];
    if ((threadIdx.x & 31) == 0) red[threadIdx.x >> 5] = s;
    __syncthreads();
    if (threadIdx.x == 0) {
        float tot = 0.f;
        for (int i = 0; i < 8; i++) tot += red[i];
        g_inv_denom[t] = 1.f / (tot + 1e-8f);
    }
}

// ======================================================================
#define FMA2(acc, a2, b2) \
    asm("fma.rn.f32x2 %0, %1, %2, %0;" : "+l"(acc) : "l"(a2), "l"(b2))
#define DUP32(d, s) \
    asm("mov.b64 %0, {%1, %1};" : "=l"(d) : "r"(s))

// flag-array barrier: one STG per block, block 0 gathers, no atomic contention
__device__ __forceinline__ void grid_sync(int& gen) {
    gen++;
    __threadfence();
    __syncthreads();
    if (blockIdx.x == 0) {
        int tid = threadIdx.x;
        if (tid > 0 && tid < NBLK) {
            while (g_arrive[tid] - gen < 0) { }
        }
        __syncthreads();
        if (tid == 0) g_release = gen;
    } else {
        if (threadIdx.x == 0) {
            g_arrive[blockIdx.x] = gen;
            while (g_release - gen < 0) { }
        }
    }
    __syncthreads();
    __threadfence();
}

__global__ void __launch_bounds__(256, 1)
rits_persistent(const float* __restrict__ x,
                const float* __restrict__ m,
                const float* __restrict__ target_x,
                const float* __restrict__ target_mask,
                const float* __restrict__ hist_b,
                const float* __restrict__ feat_b,
                float* __restrict__ out) {
    // P4: sA[128][33] (4224) + sB[32][132] (4224) = 8448 floats (33.8KB)
    // P1 aliases: sA 32x33, sB 32x34.  P2 aliases: s2A 16x132, s2B 128x17, sred @4300
    __shared__ __align__(16) float smem[8448];
    __shared__ int s_last;
    float* sA = smem;
    float* sB = smem + 4224;
    float* s2A = smem;                 // [16][132]
    float* s2B = smem + 2112;          // [128][17]
    float* sred = smem + 4300;

    const int tid = threadIdx.x;
    const int bid = blockIdx.x;

    int gen = g_release;

    // init state
    for (int i = bid * 256 + tid; i < Bsz * Hsz; i += NBLK * 256) {
        g_h[i] = 0.f; g_c[i] = 0.f;
    }
    grid_sync(gen);

    const int tx = tid & 15, ty = tid >> 4;

    // P1 decode: 32 tiles (8 row x 4 col of 32x32) x 4-way K-split
    const int tile1 = bid >> 2, ks1 = bid & 3;
    const int r0_1 = (tile1 >> 2) * 32, n0_1 = (tile1 & 3) * 32;
    const bool wr_xvec = ((tile1 & 3) == 0);

    // P2 decode: 128 tiles of 16x16
    const int r0_2 = (bid >> 3) * 16, n0_2 = (bid & 7) * 16;

    // P4 decode: 32 tiles (2 row x 16 col of 128x128) x 4-way K-split (192)
    const int ks4  = bid & 3;
    const int tile4 = bid >> 2;
    const int b0B = (tile4 >> 4) * 128;
    const int n0_4 = (tile4 & 15) * 128;
    const int k0b = ks4 * 192;

#pragma unroll 1
    for (int t = 0; t < Tsz; t++) {
        // ================= P1: x_hist GEMM (decay folded into A-load) =================
        {
            ull acc0 = 0ull, acc1 = 0ull;
#pragma unroll 1
            for (int kb = 0; kb < 4; kb++) {
                const int k0 = ks1 * 128 + kb * 32;
                __syncthreads();
#pragma unroll
                for (int q = 0; q < 4; q++) {
                    int i = tid + q * 256;
                    int r = i >> 5, k = i & 31;
                    float hv = g_h[(r0_1 + r) * Hsz + k0 + k] *
                               g_gamma_h[((size_t)(r0_1 + r) * Tsz + t) * Hsz + k0 + k];
                    sA[r * 33 + k] = hv;
                    if (wr_xvec) g_xvec[(r0_1 + r) * KC + Fsz + k0 + k] = hv;
                }
#pragma unroll
                for (int q = 0; q < 4; q++) {
                    int i = tid + q * 256;
                    int k = i >> 5, n = i & 31;
                    sB[k * 34 + n] = g_histT[(k0 + k) * Fsz + n0_1 + n];
                }
                __syncthreads();
#pragma unroll
                for (int k = 0; k < 32; k++) {
                    ull b2 = *reinterpret_cast<ull*>(&sB[k * 34 + tx * 2]);
                    ull a0d, a1d;
                    DUP32(a0d, __float_as_uint(sA[(ty * 2) * 33 + k]));
                    DUP32(a1d, __float_as_uint(sA[(ty * 2 + 1) * 33 + k]));
                    FMA2(acc0, a0d, b2);
                    FMA2(acc1, a1d, b2);
                }
            }
            size_t pb = (size_t)(tile1 * 4 + ks1) * 1024;
            *reinterpret_cast<ull*>(&g_p1part[pb + (ty * 2) * 32 + tx * 2]) = acc0;
            *reinterpret_cast<ull*>(&g_p1part[pb + (ty * 2 + 1) * 32 + tx * 2]) = acc1;
            __threadfence();
            __syncthreads();
            if (tid == 0) {
                int old = atomicAdd(&g_cnt1[tile1], 1);
                s_last = (old == 3);
            }
            __syncthreads();
            if (s_last) {
                __threadfence();
                size_t tb = (size_t)tile1 * 4 * 1024;
                for (int idx = tid; idx < 1024; idx += 256) {
                    int r = idx >> 5, n = idx & 31;
                    float v = ((g_p1part[tb + idx] + g_p1part[tb + 1024 + idx]) +
                               (g_p1part[tb + 2048 + idx] + g_p1part[tb + 3072 + idx])) +
                              hist_b[n0_1 + n];
                    g_xhist[(r0_1 + r) * Fsz + n0_1 + n] = v;
                }
                __syncthreads();
                if (tid == 0) g_cnt1[tile1] = 0;
            }
        }
        grid_sync(gen);

        // ================= P2: z_h GEMM + elementwise epilogue + loss =================
        {
#pragma unroll
            for (int q = 0; q < 8; q++) {
                int i = tid + q * 256;
                int r = i >> 7, k = i & 127;
                size_t base = ((size_t)(r0_2 + r) * Tsz + t) * Fsz + k;
                float mv = m[base], xv = x[base];
                float xh = g_xhist[(r0_2 + r) * Fsz + k];
                s2A[r * 132 + k] = mv * xv + (1.f - mv) * xh;
            }
#pragma unroll
            for (int q = 0; q < 8; q++) {
                int i = tid + q * 256;
                int k = i >> 4, n = i & 15;
                s2B[k * 17 + n] = g_featMT[k * Fsz + n0_2 + n];
            }
            __syncthreads();
            int rl = tid >> 4, nl = tid & 15;
            float z0 = 0.f, z1 = 0.f, z2 = 0.f, z3 = 0.f;
#pragma unroll 8
            for (int k = 0; k < 128; k += 4) {
                z0 += s2A[rl * 132 + k]     * s2B[(k)     * 17 + nl];
                z1 += s2A[rl * 132 + k + 1] * s2B[(k + 1) * 17 + nl];
                z2 += s2A[rl * 132 + k + 2] * s2B[(k + 2) * 17 + nl];
                z3 += s2A[rl * 132 + k + 3] * s2B[(k + 3) * 17 + nl];
            }
            int r = r0_2 + rl, n = n0_2 + nl;
            size_t base = ((size_t)r * Tsz + t) * Fsz + n;
            float z = ((z0 + z1) + (z2 + z3)) + feat_b[n];
            float xh = g_xhist[r * Fsz + n];
            float a = g_alpha[base];
            float mv = m[base], xv = x[base];
            float ch = a * z + (1.f - a) * xh;
            float cc = mv * xv + (1.f - mv) * ch;
            g_xvec[r * KC + n] = cc;
            g_xvec[r * KC + (Fsz + Hsz) + n] = mv;
            out[base] = cc;
            float ev = target_mask[base];
            float tg = target_x[base];
            float d1 = xh - tg, d2 = z - tg, d3 = ch - tg;
            float lp = ev * (d1 * d1 + d2 * d2 + d3 * d3);
            for (int o = 16; o; o >>= 1) lp += __shfl_down_sync(0xffffffffu, lp, o);
            if ((tid & 31) == 0) sred[tid >> 5] = lp;
            __syncthreads();
            if (tid == 0) {
                float tot = 0.f;
                for (int i = 0; i < 8; i++) tot += sred[i];
                g_losspart[t * 128 + bid] = tot;
            }
        }
        grid_sync(gen);

        // ================= P4: gate GEMM 128x128x192 split-K + LSTM epilogue =================
        {
            ull acc[8][4];
#pragma unroll
            for (int i = 0; i < 8; i++)
#pragma unroll
                for (int j = 0; j < 4; j++) acc[i][j] = 0ull;

            // prefetch chunk 0 into registers
            float4 pa[4], pb[4];
#pragma unroll
            for (int q = 0; q < 4; q++) {
                int i = tid + q * 256;
                int mm = i >> 3, kq = i & 7;
                pa[q] = *reinterpret_cast<const float4*>(
                    &g_xvec[(b0B + mm) * KC + k0b + kq * 4]);
            }
#pragma unroll
            for (int q = 0; q < 4; q++) {
                int i = tid + q * 256;
                int kk = i >> 5, nq = i & 31;
                pb[q] = *reinterpret_cast<const float4*>(
                    &g_WcombT[(size_t)(k0b + kk) * N4H + n0_4 + nq * 4]);
            }

#pragma unroll 1
            for (int kb = 0; kb < 6; kb++) {
                __syncthreads();
#pragma unroll
                for (int q = 0; q < 4; q++) {
                    int i = tid + q * 256;
                    int mm = i >> 3, kq = i & 7;
                    float* dst = &sA[mm * 33 + kq * 4];
                    dst[0] = pa[q].x; dst[1] = pa[q].y; dst[2] = pa[q].z; dst[3] = pa[q].w;
                }
#pragma unroll
                for (int q = 0; q < 4; q++) {
                    int i = tid + q * 256;
                    int kk = i >> 5, nq = i & 31;
                    *reinterpret_cast<float4*>(&sB[kk * 132 + nq * 4]) = pb[q];
                }
                __syncthreads();
                if (kb < 5) {
                    const int k0n = k0b + (kb + 1) * 32;
#pragma unroll
                    for (int q = 0; q < 4; q++) {
                        int i = tid + q * 256;
                        int mm = i >> 3, kq = i & 7;
                        pa[q] = *reinterpret_cast<const float4*>(
                            &g_xvec[(b0B + mm) * KC + k0n + kq * 4]);
                    }
#pragma unroll
                    for (int q = 0; q < 4; q++) {
                        int i = tid + q * 256;
                        int kk = i >> 5, nq = i & 31;
                        pb[q] = *reinterpret_cast<const float4*>(
                            &g_WcombT[(size_t)(k0n + kk) * N4H + n0_4 + nq * 4]);
                    }
                }
#pragma unroll 8
                for (int k = 0; k < 32; k++) {
                    const unsigned* arow = reinterpret_cast<const unsigned*>(sA) + k;
                    ull ad[8];
#pragma unroll
                    for (int r2 = 0; r2 < 8; r2++) {
                        unsigned av = arow[(ty * 8 + r2) * 33];
                        DUP32(ad[r2], av);
                    }
                    ulonglong2 bb0 = *reinterpret_cast<const ulonglong2*>(
                        &sB[k * 132 + tx * 8]);
                    ulonglong2 bb1 = *reinterpret_cast<const ulonglong2*>(
                        &sB[k * 132 + tx * 8 + 4]);
#pragma unroll
                    for (int r2 = 0; r2 < 8; r2++) {
                        FMA2(acc[r2][0], ad[r2], bb0.x);
                        FMA2(acc[r2][1], ad[r2], bb0.y);
                        FMA2(acc[r2][2], ad[r2], bb1.x);
                        FMA2(acc[r2][3], ad[r2], bb1.y);
                    }
                }
            }

            size_t pbase = (size_t)(tile4 * 4 + ks4) * 16384;
#pragma unroll
            for (int r2 = 0; r2 < 8; r2++) {
#pragma unroll
                for (int cp = 0; cp < 4; cp++) {
                    size_t off = pbase + (size_t)(ty * 8 + r2) * 128 + tx * 8 + cp * 2;
                    *reinterpret_cast<ull*>(&g_part[off]) = acc[r2][cp];
                }
            }
            __threadfence();
            __syncthreads();
            if (tid == 0) {
                int old = atomicAdd(&g_tilecnt[tile4], 1);
                s_last = (old == 3);
            }
            __syncthreads();
            if (s_last) {
                __threadfence();
                size_t tb = (size_t)tile4 * 4 * 16384;
                for (int idx = tid; idx < 4096; idx += 256) {
                    int row = idx >> 5, u = idx & 31;
                    size_t go_off = (size_t)row * 128 + u * 4;
                    float4 p0 = *reinterpret_cast<const float4*>(&g_part[tb + go_off]);
                    float4 p1 = *reinterpret_cast<const float4*>(&g_part[tb + 16384 + go_off]);
                    float4 p2 = *reinterpret_cast<const float4*>(&g_part[tb + 32768 + go_off]);
                    float4 p3 = *reinterpret_cast<const float4*>(&g_part[tb + 49152 + go_off]);
                    float gi = ((p0.x + p1.x) + (p2.x + p3.x)) + g_bcomb[n0_4 + u * 4 + 0];
                    float gf = ((p0.y + p1.y) + (p2.y + p3.y)) + g_bcomb[n0_4 + u * 4 + 1];
                    float gg = ((p0.z + p1.z) + (p2.z + p3.z)) + g_bcomb[n0_4 + u * 4 + 2];
                    float gO = ((p0.w + p1.w) + (p2.w + p3.w)) + g_bcomb[n0_4 + u * 4 + 3];
                    float si = 1.f / (1.f + expf(-gi));
                    float sf = 1.f / (1.f + expf(-gf));
                    float so = 1.f / (1.f + expf(-gO));
                    float tg = tanhf(gg);
                    int b = b0B + row;
                    int j = (n0_4 >> 2) + u;
                    float cn = sf * g_c[b * Hsz + j] + si * tg;
                    g_c[b * Hsz + j] = cn;
                    g_h[b * Hsz + j] = so * tanhf(cn);
                }
                __syncthreads();
                if (tid == 0) g_tilecnt[tile4] = 0;
            }
        }
        grid_sync(gen);
    }
}

// ----------------------------------------------------------------------
__global__ void loss_final(float* __restrict__ out, int out_size) {
    __shared__ float s[128];
    int t = threadIdx.x;
    float v = 0.f;
    for (int p = 0; p < 128; p++) v += g_losspart[t * 128 + p];
    s[t] = v * g_inv_denom[t];
    __syncthreads();
    if (t == 0) {
        float tot = 0.f;
        for (int i = 0; i < 128; i++) tot += s[i];
        out[out_size - 1] = tot / (float)Tsz;
    }
}

// ----------------------------------------------------------------------
extern "C" void kernel_launch(void* const* d_in, const int* in_sizes, int n_in,
                              void* d_out, int out_size) {
    const float* x           = (const float*)d_in[0];
    const float* m           = (const float*)d_in[1];
    const float* d           = (const float*)d_in[2];
    const float* target_x    = (const float*)d_in[3];
    const float* target_mask = (const float*)d_in[4];
    const float* td_h_W      = (const float*)d_in[5];
    const float* td_h_b      = (const float*)d_in[6];
    const float* td_x_W      = (const float*)d_in[7];
    const float* td_x_b      = (const float*)d_in[8];
    const float* hist_W      = (const float*)d_in[9];
    const float* hist_b      = (const float*)d_in[10];
    const float* feat_W      = (const float*)d_in[11];
    const float* feat_b      = (const float*)d_in[12];
    const float* wc_W        = (const float*)d_in[13];
    const float* wc_b        = (const float*)d_in[14];
    const float* W_ih        = (const float*)d_in[15];
    const float* W_hh        = (const float*)d_in[16];
    const float* b_ih        = (const float*)d_in[17];
    const float* b_hh        = (const float*)d_in[18];
    float* out = (float*)d_out;

    prep_weights<<<512, 256>>>(td_h_W, hist_W, feat_W, wc_W, W_ih, W_hh, b_ih, b_hh);
    gammax_kernel<<<(BT * Fsz + 255) / 256, 256>>>(d, td_x_W, td_x_b);
    gammah_gemm<<<dim3(BT / 64, Hsz / 64), 256>>>(d, td_h_b);
    alpha_gemm<<<dim3(BT / 64, Fsz / 64), 256>>>(m, wc_b);
    denom_kernel<<<Tsz, 256>>>(target_mask);

    rits_persistent<<<NBLK, 256>>>(x, m, target_x, target_mask, hist_b, feat_b, out);

    loss_final<<<1, 128>>>(out, out_size);
}

// round 8
// speedup vs baseline: 2.1776x; 1.0725x over previous
#include <cuda_runtime.h>
#include <math.h>

#define Bsz 256
#define Tsz 128
#define Fsz 128
#define Hsz 512
#define BT  (Bsz * Tsz)          // 32768
#define KC  768                  // c_c(128) + h_dec(512) + m(128)
#define N4H 2048                 // 4*H, gate-interleaved
#define NBLK 128                 // persistent grid size

typedef unsigned long long ull;

// ----- device scratch (allocation-free rule: __device__ globals) -----
__device__ __align__(16) float g_h[Bsz * Hsz];
__device__ __align__(16) float g_c[Bsz * Hsz];
__device__ __align__(16) float g_xvec[Bsz * KC];
__device__ __align__(16) float g_xhist[Bsz * Fsz];
__device__ __align__(16) float g_gamma_h[(size_t)BT * Hsz];   // 64 MB
__device__ __align__(16) float g_alpha[BT * Fsz];
__device__ float g_losspart[Tsz * 128];
__device__ float g_maskpart[Tsz * 128];
__device__ __align__(16) float g_tdhT[Fsz * Hsz];
__device__ __align__(16) float g_histT[Hsz * Fsz];
__device__ __align__(16) float g_featMT[Fsz * Fsz];
__device__ __align__(16) float g_wcT[2 * Fsz * Fsz];
__device__ __align__(16) float g_WcombT[KC * N4H];
__device__ __align__(16) float g_bcomb[N4H];
__device__ __align__(16) float g_part[(size_t)32 * 4 * 128 * 128];  // P4 split-K partials
__device__ __align__(16) float g_p1part[32 * 4 * 1024];             // P1 split-K partials
__device__ int g_tilecnt[32];
__device__ int g_cnt1[32];
__device__ volatile int g_x1flag[32];    // P1 tile-done flags (monotone per step)

// flag-array grid barrier
__device__ volatile int g_arrive[NBLK];
__device__ volatile int g_release;

__device__ __forceinline__ float fsigmoid(float v) {
    return __fdividef(1.f, 1.f + __expf(-v));
}
__device__ __forceinline__ float ftanh(float v) {
    return __fdividef(2.f, 1.f + __expf(-2.f * v)) - 1.f;
}

// ----------------------------------------------------------------------
__global__ void prep_weights(const float* __restrict__ td_h_W,
                             const float* __restrict__ hist_W,
                             const float* __restrict__ feat_W,
                             const float* __restrict__ wc_W,
                             const float* __restrict__ W_ih,
                             const float* __restrict__ W_hh,
                             const float* __restrict__ b_ih,
                             const float* __restrict__ b_hh) {
    int stride = gridDim.x * blockDim.x;
    int tid = blockIdx.x * blockDim.x + threadIdx.x;
    for (int i = tid; i < Fsz * Hsz; i += stride) {
        int k = i / Hsz, n = i % Hsz;
        g_tdhT[i] = td_h_W[n * Fsz + k];
    }
    for (int i = tid; i < Hsz * Fsz; i += stride) {
        int k = i / Fsz, f = i % Fsz;
        g_histT[i] = hist_W[f * Hsz + k];
    }
    for (int i = tid; i < Fsz * Fsz; i += stride) {
        int j = i / Fsz, f = i % Fsz;
        g_featMT[i] = (j == f) ? 0.f : feat_W[f * Fsz + j];
    }
    for (int i = tid; i < 2 * Fsz * Fsz; i += stride) {
        int k = i / Fsz, n = i % Fsz;
        g_wcT[i] = wc_W[n * 2 * Fsz + k];
    }
    for (int i = tid; i < KC * N4H; i += stride) {
        int k = i / N4H, n = i % N4H;
        int j = n >> 2, g = n & 3;
        int row = g * Hsz + j;
        float v;
        if (k < Fsz)            v = W_ih[row * (2 * Fsz) + k];
        else if (k < Fsz + Hsz) v = W_hh[row * Hsz + (k - Fsz)];
        else                    v = W_ih[row * (2 * Fsz) + Fsz + (k - Fsz - Hsz)];
        g_WcombT[i] = v;
    }
    for (int i = tid; i < N4H; i += stride) {
        int j = i >> 2, g = i & 3;
        g_bcomb[i] = b_ih[g * Hsz + j] + b_hh[g * Hsz + j];
    }
}

// ----------------------------------------------------------------------
// gamma_h GEMM: M=BT, N=512, K=128
// ----------------------------------------------------------------------
__global__ void gammah_gemm(const float* __restrict__ d,
                            const float* __restrict__ td_h_b) {
    __shared__ float sA[64][33];
    __shared__ float sB[32][64];
    int m0 = blockIdx.x * 64;
    int n0 = blockIdx.y * 64;
    int tid = threadIdx.x;
    int tx = tid & 15, ty = tid >> 4;
    float acc[4][4] = {};
    for (int kk = 0; kk < Fsz; kk += 32) {
        for (int i = tid; i < 64 * 32; i += 256) {
            int r = i >> 5, k = i & 31;
            sA[r][k] = d[(size_t)(m0 + r) * Fsz + kk + k];
        }
        for (int i = tid; i < 32 * 64; i += 256) {
            int k = i >> 6, n = i & 63;
            sB[k][n] = g_tdhT[(kk + k) * Hsz + n0 + n];
        }
        __syncthreads();
#pragma unroll
        for (int k = 0; k < 32; k++) {
            float a[4], b[4];
#pragma unroll
            for (int i = 0; i < 4; i++) a[i] = sA[ty + i * 16][k];
#pragma unroll
            for (int j = 0; j < 4; j++) b[j] = sB[k][tx + j * 16];
#pragma unroll
            for (int i = 0; i < 4; i++)
#pragma unroll
                for (int j = 0; j < 4; j++) acc[i][j] += a[i] * b[j];
        }
        __syncthreads();
    }
#pragma unroll
    for (int i = 0; i < 4; i++)
#pragma unroll
        for (int j = 0; j < 4; j++) {
            int n = n0 + tx + j * 16;
            int row = m0 + ty + i * 16;
            g_gamma_h[(size_t)row * Hsz + n] = __expf(-fmaxf(acc[i][j] + td_h_b[n], 0.f));
        }
}

// ----------------------------------------------------------------------
// alpha GEMM M=BT, N=128, K=256 — gamma_x computed inline in the A-load
// ----------------------------------------------------------------------
__global__ void alpha_gemm(const float* __restrict__ d,
                           const float* __restrict__ m,
                           const float* __restrict__ td_x_W,
                           const float* __restrict__ td_x_b,
                           const float* __restrict__ wc_b) {
    __shared__ float sA[64][33];
    __shared__ float sB[32][64];
    int m0 = blockIdx.x * 64;
    int n0 = blockIdx.y * 64;
    int tid = threadIdx.x;
    int tx = tid & 15, ty = tid >> 4;
    float acc[4][4] = {};
    for (int kk = 0; kk < 2 * Fsz; kk += 32) {
        for (int i = tid; i < 64 * 32; i += 256) {
            int r = i >> 5, k = i & 31;
            int kg = kk + k;
            float v;
            if (kg < Fsz) {
                float dv = d[(size_t)(m0 + r) * Fsz + kg];
                float u = dv * td_x_W[kg * Fsz + kg] + td_x_b[kg];
                v = __expf(-fmaxf(u, 0.f));
            } else {
                v = m[(size_t)(m0 + r) * Fsz + (kg - Fsz)];
            }
            sA[r][k] = v;
        }
        for (int i = tid; i < 32 * 64; i += 256) {
            int k = i >> 6, n = i & 63;
            sB[k][n] = g_wcT[(kk + k) * Fsz + n0 + n];
        }
        __syncthreads();
#pragma unroll
        for (int k = 0; k < 32; k++) {
            float a[4], b[4];
#pragma unroll
            for (int i = 0; i < 4; i++) a[i] = sA[ty + i * 16][k];
#pragma unroll
            for (int j = 0; j < 4; j++) b[j] = sB[k][tx + j * 16];
#pragma unroll
            for (int i = 0; i < 4; i++)
#pragma unroll
                for (int j = 0; j < 4; j++) acc[i][j] += a[i] * b[j];
        }
        __syncthreads();
    }
#pragma unroll
    for (int i = 0; i < 4; i++)
#pragma unroll
        for (int j = 0; j < 4; j++) {
            int n = n0 + tx + j * 16;
            int row = m0 + ty + i * 16;
            float v = acc[i][j] + wc_b[n];
            g_alpha[row * Fsz + n] = fsigmoid(v);
        }
}

// ======================================================================
#define FMA2(acc, a2, b2) \
    asm("fma.rn.f32x2 %0, %1, %2, %0;" : "+l"(acc) : "l"(a2), "l"(b2))
#define DUP32(d, s) \
    asm("mov.b64 %0, {%1, %1};" : "=l"(d) : "r"(s))

// flag-array barrier: one STG per block, block 0 gathers, no atomic contention
__device__ __forceinline__ void grid_sync(int& gen) {
    gen++;
    __threadfence();
    __syncthreads();
    if (blockIdx.x == 0) {
        int tid = threadIdx.x;
        if (tid > 0 && tid < NBLK) {
            while (g_arrive[tid] - gen < 0) { }
        }
        __syncthreads();
        if (tid == 0) g_release = gen;
    } else {
        if (threadIdx.x == 0) {
            g_arrive[blockIdx.x] = gen;
            while (g_release - gen < 0) { }
        }
    }
    __syncthreads();
    __threadfence();
}

__global__ void __launch_bounds__(256, 1)
rits_persistent(const float* __restrict__ x,
                const float* __restrict__ m,
                const float* __restrict__ target_x,
                const float* __restrict__ target_mask,
                const float* __restrict__ hist_b,
                const float* __restrict__ feat_b,
                float* __restrict__ out) {
    // P4: sA[128][33] (4224) + sB[32][132] (4224) = 8448 floats (33.8KB)
    // P1 aliases: sA 32x33, sB 32x34.  P2 aliases: s2A 16x132, s2B 128x17, sred @4300
    __shared__ __align__(16) float smem[8448];
    __shared__ int s_last;
    float* sA = smem;
    float* sB = smem + 4224;
    float* s2A = smem;                 // [16][132]
    float* s2B = smem + 2112;          // [128][17]
    float* sred = smem + 4300;         // 8
    float* sred2 = smem + 4316;        // 8

    const int tid = threadIdx.x;
    const int bid = blockIdx.x;

    int gen = g_release;

    // init state (+ reset P1 flags each replay)
    for (int i = bid * 256 + tid; i < Bsz * Hsz; i += NBLK * 256) {
        g_h[i] = 0.f; g_c[i] = 0.f;
    }
    if (bid == 0 && tid < 32) g_x1flag[tid] = 0;
    grid_sync(gen);

    const int tx = tid & 15, ty = tid >> 4;

    // P1 decode: 32 tiles (8 row x 4 col of 32x32) x 4-way K-split
    const int tile1 = bid >> 2, ks1 = bid & 3;
    const int r0_1 = (tile1 >> 2) * 32, n0_1 = (tile1 & 3) * 32;
    const bool wr_xvec = ((tile1 & 3) == 0);

    // P2 decode: 128 tiles of 16x16; needs x_hist tiles (rb, 0..3)
    const int r0_2 = (bid >> 3) * 16, n0_2 = (bid & 7) * 16;
    const int rb = bid >> 4;

    // P4 decode: 32 tiles (2 row x 16 col of 128x128) x 4-way K-split (192)
    const int ks4  = bid & 3;
    const int tile4 = bid >> 2;
    const int b0B = (tile4 >> 4) * 128;
    const int n0_4 = (tile4 & 15) * 128;
    const int k0b = ks4 * 192;

#pragma unroll 1
    for (int t = 0; t < Tsz; t++) {
        // ================= P1: x_hist GEMM (decay folded into A-load) =================
        {
            ull acc0 = 0ull, acc1 = 0ull;
#pragma unroll 1
            for (int kb = 0; kb < 4; kb++) {
                const int k0 = ks1 * 128 + kb * 32;
                __syncthreads();
#pragma unroll
                for (int q = 0; q < 4; q++) {
                    int i = tid + q * 256;
                    int r = i >> 5, k = i & 31;
                    float hv = g_h[(r0_1 + r) * Hsz + k0 + k] *
                               g_gamma_h[((size_t)(r0_1 + r) * Tsz + t) * Hsz + k0 + k];
                    sA[r * 33 + k] = hv;
                    if (wr_xvec) g_xvec[(r0_1 + r) * KC + Fsz + k0 + k] = hv;
                }
#pragma unroll
                for (int q = 0; q < 4; q++) {
                    int i = tid + q * 256;
                    int k = i >> 5, n = i & 31;
                    sB[k * 34 + n] = g_histT[(k0 + k) * Fsz + n0_1 + n];
                }
                __syncthreads();
#pragma unroll
                for (int k = 0; k < 32; k++) {
                    ull b2 = *reinterpret_cast<ull*>(&sB[k * 34 + tx * 2]);
                    ull a0d, a1d;
                    DUP32(a0d, __float_as_uint(sA[(ty * 2) * 33 + k]));
                    DUP32(a1d, __float_as_uint(sA[(ty * 2 + 1) * 33 + k]));
                    FMA2(acc0, a0d, b2);
                    FMA2(acc1, a1d, b2);
                }
            }
            size_t pb = (size_t)(tile1 * 4 + ks1) * 1024;
            *reinterpret_cast<ull*>(&g_p1part[pb + (ty * 2) * 32 + tx * 2]) = acc0;
            *reinterpret_cast<ull*>(&g_p1part[pb + (ty * 2 + 1) * 32 + tx * 2]) = acc1;
            __threadfence();
            __syncthreads();
            if (tid == 0) {
                int old = atomicAdd(&g_cnt1[tile1], 1);
                s_last = (old == 3);
            }
            __syncthreads();
            if (s_last) {
                __threadfence();
                size_t tb = (size_t)tile1 * 4 * 1024;
                for (int idx = tid; idx < 1024; idx += 256) {
                    int r = idx >> 5, n = idx & 31;
                    float v = ((g_p1part[tb + idx] + g_p1part[tb + 1024 + idx]) +
                               (g_p1part[tb + 2048 + idx] + g_p1part[tb + 3072 + idx])) +
                              hist_b[n0_1 + n];
                    g_xhist[(r0_1 + r) * Fsz + n0_1 + n] = v;
                }
                __threadfence();
                __syncthreads();
                if (tid == 0) {
                    g_cnt1[tile1] = 0;
                    g_x1flag[tile1] = t + 1;   // publish
                }
            }
        }

        // ================= P2: z_h GEMM + elementwise epilogue + loss =================
        {
            // wait for the 4 x_hist tiles covering rows [rb*32, rb*32+32)
            if (tid < 4) {
                while (g_x1flag[rb * 4 + tid] - (t + 1) < 0) { }
            }
            __syncthreads();
            __threadfence();   // acquire

#pragma unroll
            for (int q = 0; q < 8; q++) {
                int i = tid + q * 256;
                int r = i >> 7, k = i & 127;
                size_t base = ((size_t)(r0_2 + r) * Tsz + t) * Fsz + k;
                float mv = m[base], xv = x[base];
                float xh = g_xhist[(r0_2 + r) * Fsz + k];
                s2A[r * 132 + k] = mv * xv + (1.f - mv) * xh;
            }
#pragma unroll
            for (int q = 0; q < 8; q++) {
                int i = tid + q * 256;
                int k = i >> 4, n = i & 15;
                s2B[k * 17 + n] = g_featMT[k * Fsz + n0_2 + n];
            }
            __syncthreads();
            int rl = tid >> 4, nl = tid & 15;
            float z0 = 0.f, z1 = 0.f, z2 = 0.f, z3 = 0.f;
#pragma unroll 8
            for (int k = 0; k < 128; k += 4) {
                z0 += s2A[rl * 132 + k]     * s2B[(k)     * 17 + nl];
                z1 += s2A[rl * 132 + k + 1] * s2B[(k + 1) * 17 + nl];
                z2 += s2A[rl * 132 + k + 2] * s2B[(k + 2) * 17 + nl];
                z3 += s2A[rl * 132 + k + 3] * s2B[(k + 3) * 17 + nl];
            }
            int r = r0_2 + rl, n = n0_2 + nl;
            size_t base = ((size_t)r * Tsz + t) * Fsz + n;
            float z = ((z0 + z1) + (z2 + z3)) + feat_b[n];
            float xh = g_xhist[r * Fsz + n];
            float a = g_alpha[base];
            float mv = m[base], xv = x[base];
            float ch = a * z + (1.f - a) * xh;
            float cc = mv * xv + (1.f - mv) * ch;
            g_xvec[r * KC + n] = cc;
            g_xvec[r * KC + (Fsz + Hsz) + n] = mv;
            out[base] = cc;
            float ev = target_mask[base];
            float tg = target_x[base];
            float d1 = xh - tg, d2 = z - tg, d3 = ch - tg;
            float lp = ev * (d1 * d1 + d2 * d2 + d3 * d3);
            float es = ev;
            for (int o = 16; o; o >>= 1) {
                lp += __shfl_down_sync(0xffffffffu, lp, o);
                es += __shfl_down_sync(0xffffffffu, es, o);
            }
            if ((tid & 31) == 0) { sred[tid >> 5] = lp; sred2[tid >> 5] = es; }
            __syncthreads();
            if (tid == 0) {
                float tot = 0.f, tot2 = 0.f;
                for (int i = 0; i < 8; i++) { tot += sred[i]; tot2 += sred2[i]; }
                g_losspart[t * 128 + bid] = tot;
                g_maskpart[t * 128 + bid] = tot2;
            }
        }
        grid_sync(gen);

        // ================= P4: gate GEMM 128x128x192 split-K + LSTM epilogue =================
        {
            ull acc[8][4];
#pragma unroll
            for (int i = 0; i < 8; i++)
#pragma unroll
                for (int j = 0; j < 4; j++) acc[i][j] = 0ull;

            // prefetch chunk 0 into registers
            float4 pa[4], pb[4];
#pragma unroll
            for (int q = 0; q < 4; q++) {
                int i = tid + q * 256;
                int mm = i >> 3, kq = i & 7;
                pa[q] = *reinterpret_cast<const float4*>(
                    &g_xvec[(b0B + mm) * KC + k0b + kq * 4]);
            }
#pragma unroll
            for (int q = 0; q < 4; q++) {
                int i = tid + q * 256;
                int kk = i >> 5, nq = i & 31;
                pb[q] = *reinterpret_cast<const float4*>(
                    &g_WcombT[(size_t)(k0b + kk) * N4H + n0_4 + nq * 4]);
            }

#pragma unroll 1
            for (int kb = 0; kb < 6; kb++) {
                __syncthreads();
#pragma unroll
                for (int q = 0; q < 4; q++) {
                    int i = tid + q * 256;
                    int mm = i >> 3, kq = i & 7;
                    float* dst = &sA[mm * 33 + kq * 4];
                    dst[0] = pa[q].x; dst[1] = pa[q].y; dst[2] = pa[q].z; dst[3] = pa[q].w;
                }
#pragma unroll
                for (int q = 0; q < 4; q++) {
                    int i = tid + q * 256;
                    int kk = i >> 5, nq = i & 31;
                    *reinterpret_cast<float4*>(&sB[kk * 132 + nq * 4]) = pb[q];
                }
                __syncthreads();
                if (kb < 5) {
                    const int k0n = k0b + (kb + 1) * 32;
#pragma unroll
                    for (int q = 0; q < 4; q++) {
                        int i = tid + q * 256;
                        int mm = i >> 3, kq = i & 7;
                        pa[q] = *reinterpret_cast<const float4*>(
                            &g_xvec[(b0B + mm) * KC + k0n + kq * 4]);
                    }
#pragma unroll
                    for (int q = 0; q < 4; q++) {
                        int i = tid + q * 256;
                        int kk = i >> 5, nq = i & 31;
                        pb[q] = *reinterpret_cast<const float4*>(
                            &g_WcombT[(size_t)(k0n + kk) * N4H + n0_4 + nq * 4]);
                    }
                }
#pragma unroll 8
                for (int k = 0; k < 32; k++) {
                    const unsigned* arow = reinterpret_cast<const unsigned*>(sA) + k;
                    ull ad[8];
#pragma unroll
                    for (int r2 = 0; r2 < 8; r2++) {
                        unsigned av = arow[(ty * 8 + r2) * 33];
                        DUP32(ad[r2], av);
                    }
                    ulonglong2 bb0 = *reinterpret_cast<const ulonglong2*>(
                        &sB[k * 132 + tx * 8]);
                    ulonglong2 bb1 = *reinterpret_cast<const ulonglong2*>(
                        &sB[k * 132 + tx * 8 + 4]);
#pragma unroll
                    for (int r2 = 0; r2 < 8; r2++) {
                        FMA2(acc[r2][0], ad[r2], bb0.x);
                        FMA2(acc[r2][1], ad[r2], bb0.y);
                        FMA2(acc[r2][2], ad[r2], bb1.x);
                        FMA2(acc[r2][3], ad[r2], bb1.y);
                    }
                }
            }

            size_t pbase = (size_t)(tile4 * 4 + ks4) * 16384;
#pragma unroll
            for (int r2 = 0; r2 < 8; r2++) {
#pragma unroll
                for (int cp = 0; cp < 4; cp++) {
                    size_t off = pbase + (size_t)(ty * 8 + r2) * 128 + tx * 8 + cp * 2;
                    *reinterpret_cast<ull*>(&g_part[off]) = acc[r2][cp];
                }
            }
            __threadfence();
            __syncthreads();
            if (tid == 0) {
                int old = atomicAdd(&g_tilecnt[tile4], 1);
                s_last = (old == 3);
            }
            __syncthreads();
            if (s_last) {
                __threadfence();
                size_t tb = (size_t)tile4 * 4 * 16384;
                for (int idx = tid; idx < 4096; idx += 256) {
                    int row = idx >> 5, u = idx & 31;
                    size_t go_off = (size_t)row * 128 + u * 4;
                    float4 p0 = *reinterpret_cast<const float4*>(&g_part[tb + go_off]);
                    float4 p1 = *reinterpret_cast<const float4*>(&g_part[tb + 16384 + go_off]);
                    float4 p2 = *reinterpret_cast<const float4*>(&g_part[tb + 32768 + go_off]);
                    float4 p3 = *reinterpret_cast<const float4*>(&g_part[tb + 49152 + go_off]);
                    float gi = ((p0.x + p1.x) + (p2.x + p3.x)) + g_bcomb[n0_4 + u * 4 + 0];
                    float gf = ((p0.y + p1.y) + (p2.y + p3.y)) + g_bcomb[n0_4 + u * 4 + 1];
                    float gg = ((p0.z + p1.z) + (p2.z + p3.z)) + g_bcomb[n0_4 + u * 4 + 2];
                    float gO = ((p0.w + p1.w) + (p2.w + p3.w)) + g_bcomb[n0_4 + u * 4 + 3];
                    float si = fsigmoid(gi);
                    float sf = fsigmoid(gf);
                    float so = fsigmoid(gO);
                    float tg = ftanh(gg);
                    int b = b0B + row;
                    int j = (n0_4 >> 2) + u;
                    float cn = sf * g_c[b * Hsz + j] + si * tg;
                    g_c[b * Hsz + j] = cn;
                    g_h[b * Hsz + j] = so * ftanh(cn);
                }
                __syncthreads();
                if (tid == 0) g_tilecnt[tile4] = 0;
            }
        }
        grid_sync(gen);
    }
}

// ----------------------------------------------------------------------
__global__ void loss_final(float* __restrict__ out, int out_size) {
    __shared__ float s[128];
    int t = threadIdx.x;
    float v = 0.f, mv = 0.f;
    for (int p = 0; p < 128; p++) {
        v += g_losspart[t * 128 + p];
        mv += g_maskpart[t * 128 + p];
    }
    s[t] = v / (mv + 1e-8f);
    __syncthreads();
    if (t == 0) {
        float tot = 0.f;
        for (int i = 0; i < 128; i++) tot += s[i];
        out[out_size - 1] = tot / (float)Tsz;
    }
}

// ----------------------------------------------------------------------
extern "C" void kernel_launch(void* const* d_in, const int* in_sizes, int n_in,
                              void* d_out, int out_size) {
    const float* x           = (const float*)d_in[0];
    const float* m           = (const float*)d_in[1];
    const float* d           = (const float*)d_in[2];
    const float* target_x    = (const float*)d_in[3];
    const float* target_mask = (const float*)d_in[4];
    const float* td_h_W      = (const float*)d_in[5];
    const float* td_h_b      = (const float*)d_in[6];
    const float* td_x_W      = (const float*)d_in[7];
    const float* td_x_b      = (const float*)d_in[8];
    const float* hist_W      = (const float*)d_in[9];
    const float* hist_b      = (const float*)d_in[10];
    const float* feat_W      = (const float*)d_in[11];
    const float* feat_b      = (const float*)d_in[12];
    const float* wc_W        = (const float*)d_in[13];
    const float* wc_b        = (const float*)d_in[14];
    const float* W_ih        = (const float*)d_in[15];
    const float* W_hh        = (const float*)d_in[16];
    const float* b_ih        = (const float*)d_in[17];
    const float* b_hh        = (const float*)d_in[18];
    float* out = (float*)d_out;

    prep_weights<<<512, 256>>>(td_h_W, hist_W, feat_W, wc_W, W_ih, W_hh, b_ih, b_hh);
    gammah_gemm<<<dim3(BT / 64, Hsz / 64), 256>>>(d, td_h_b);
    alpha_gemm<<<dim3(BT / 64, Fsz / 64), 256>>>(d, m, td_x_W, td_x_b, wc_b);

    rits_persistent<<<NBLK, 256>>>(x, m, target_x, target_mask, hist_b, feat_b, out);

    loss_final<<<1, 128>>>(out, out_size);
}